// round 2
// baseline (speedup 1.0000x reference)
#include <cuda_runtime.h>
#include <cstdint>
#include <cstddef>

// Problem dims
#define TT 512
#define BB 64
#define DD 1024
#define HH 1024
#define NG 4096              // 4*H
#define KK 1024              // contraction dim for each half
#define BH (BB*HH)           // 65536
#define BG (BB*NG)           // 262144

// -------- device scratch (no allocations allowed) --------
__device__ float g_Wx[KK*NG];                 // 16 MB  x-part weights [k][n]
__device__ float g_Wh[KK*NG];                 // 16 MB  h-part weights [k][n]
__device__ float g_ball[NG];                  // fused bias
__device__ float g_XW[(size_t)TT*BB*NG];      // 512 MB precomputed x-projections
__device__ float g_hw[BB*NG];                 // per-step recurrent gemm result
__device__ float g_c[BB*HH];                  // cell state
__device__ unsigned int g_bar[TT];            // per-step grid barriers

// ---------------- repack weights ----------------
__global__ void repack_kernel(const float* __restrict__ Wf, const float* __restrict__ Wi,
                              const float* __restrict__ Wg, const float* __restrict__ Wo,
                              const float* __restrict__ bf, const float* __restrict__ bi,
                              const float* __restrict__ bg, const float* __restrict__ bo) {
    int idx = blockIdx.x * 256 + threadIdx.x;
    if (idx >= KK * NG) return;
    int k = idx >> 12;          // / 4096
    int n = idx & (NG - 1);
    int g = n >> 10;
    int c = n & 1023;
    const float* W = (g == 0) ? Wf : (g == 1) ? Wi : (g == 2) ? Wg : Wo;
    g_Wx[idx] = W[(size_t)k * HH + c];                 // rows [0, D)
    g_Wh[idx] = W[(size_t)(k + DD) * HH + c];          // rows [D, D+H)
    if (idx < NG) {
        const float* bv = (g == 0) ? bf : (g == 1) ? bi : (g == 2) ? bg : bo;
        g_ball[idx] = bv[c];
    }
}

// ---------------- init state ----------------
__global__ void init_kernel() {
    int idx = blockIdx.x * 256 + threadIdx.x;
    if (idx < BH) g_c[idx] = 0.0f;
    if (idx < TT) g_bar[idx] = 0u;
}

// ---------------- fp32 GEMM tile 64x32, K=1024, f32x2 dual-issue ----------------
// A: row-major, ld=1024 (rows m0..m0+64).  Bm: [1024][4096].  C: [.][4096].
// Thread layout: 128 threads = 32 n-lanes x 4 m-groups; each thread: 16 m rows (8 f32x2 pairs) x 1 n col.
__device__ __forceinline__ void gemm_tile_64x32(
    const float* __restrict__ A, int m0,
    const float* __restrict__ Bm, int n0,
    float* __restrict__ C,
    const float* __restrict__ bias) {

    __shared__ float As[64][64];   // [k][m]  (transposed for broadcast reads)
    __shared__ float Bs[64][32];   // [k][n]

    const int tid = threadIdx.x;
    const int n  = tid & 31;
    const int mg = tid >> 5;

    unsigned long long acc[8];
#pragma unroll
    for (int p = 0; p < 8; p++) acc[p] = 0ull;

    for (int k0 = 0; k0 < KK; k0 += 64) {
        // Load A tile 64(m) x 64(k); lanes span m -> conflict-free STS into [k][m]
#pragma unroll
        for (int it = 0; it < 8; it++) {
            int j = tid + it * 128;          // 0..1023 float4 slots
            int m = j & 63;
            int kq = j >> 6;                 // 0..15
            float4 v = *(const float4*)(A + (size_t)(m0 + m) * 1024 + k0 + kq * 4);
            As[kq * 4 + 0][m] = v.x;
            As[kq * 4 + 1][m] = v.y;
            As[kq * 4 + 2][m] = v.z;
            As[kq * 4 + 3][m] = v.w;
        }
        // Load B tile 64(k) x 32(n), coalesced
#pragma unroll
        for (int it = 0; it < 4; it++) {
            int j = tid + it * 128;          // 0..511 float4 slots
            int kb = j >> 3;
            int nq = j & 7;
            *(float4*)&Bs[kb][nq * 4] =
                *(const float4*)(Bm + (size_t)(k0 + kb) * NG + n0 + nq * 4);
        }
        __syncthreads();

#pragma unroll 16
        for (int k = 0; k < 64; k++) {
            float bv = Bs[k][n];
            unsigned long long bp;
            asm("mov.b64 %0, {%1, %1};" : "=l"(bp) : "f"(bv));
            const float* arow = &As[k][mg * 16];
#pragma unroll
            for (int p = 0; p < 8; p++) {
                unsigned long long ap = *(const unsigned long long*)(arow + 2 * p);
                asm("fma.rn.f32x2 %0, %1, %2, %0;" : "+l"(acc[p]) : "l"(ap), "l"(bp));
            }
        }
        __syncthreads();
    }

    float badd = (bias != nullptr) ? bias[n0 + n] : 0.0f;
#pragma unroll
    for (int p = 0; p < 8; p++) {
        float lo, hi;
        asm("mov.b64 {%0, %1}, %2;" : "=f"(lo), "=f"(hi) : "l"(acc[p]));
        int m = m0 + mg * 16 + 2 * p;
        C[(size_t)m * NG + n0 + n]       = lo + badd;
        C[(size_t)(m + 1) * NG + n0 + n] = hi + badd;
    }
}

// ---------------- phase 1: XW = inputs @ Wx + b ----------------
__global__ __launch_bounds__(128) void xproj_kernel(const float* __restrict__ inputs) {
    int n0 = blockIdx.x * 32;
    int m0 = blockIdx.y * 64;
    gemm_tile_64x32(inputs, m0, g_Wx, n0, g_XW, g_ball);
}

// ---------------- per-step: hW gemm + grid barrier + cell update ----------------
__device__ __forceinline__ float sigf(float x) { return 1.0f / (1.0f + __expf(-x)); }

__device__ __forceinline__ void cell_one(float xf, float xi, float xg, float xo,
                                         float hf, float hi_, float hg, float ho,
                                         float cp, float& cn, float& hn) {
    float f = sigf(xf + hf);
    float i = sigf(xi + hi_);
    float g = tanhf(xg + hg);
    float o = sigf(xo + ho);
    cn = f * cp + i * g;
    hn = o * tanhf(cn);
}

__global__ __launch_bounds__(128) void step_kernel(const float* __restrict__ hprev,
                                                   float* __restrict__ hout,
                                                   int t) {
    const int n0 = blockIdx.x * 32;
    const float* xw = g_XW + (size_t)t * BG;

    if (hprev != nullptr) {
        gemm_tile_64x32(hprev, 0, g_Wh, n0, g_hw, nullptr);
    } else {
        // t == 0: h_{-1} = 0 -> zero this CTA's hW tile
#pragma unroll
        for (int it = 0; it < 16; it++) {
            int j = threadIdx.x + it * 128;   // 2048 = 64*32
            int m = j >> 5;
            int nn = j & 31;
            g_hw[(size_t)m * NG + n0 + nn] = 0.0f;
        }
    }

    // ---- cross-CTA barrier (128 CTAs, all resident on 148 SMs) ----
    __threadfence();
    __syncthreads();
    if (threadIdx.x == 0) {
        atomicAdd(&g_bar[t], 1u);
        while (*(volatile unsigned int*)&g_bar[t] < 128u) { }
    }
    __syncthreads();

    // ---- fused element-wise cell update: 16384 threads x 4 elems ----
    int e4 = blockIdx.x * 128 + threadIdx.x;   // 0..16383
    int e = e4 * 4;                            // element index into [B][H]
    int b = e >> 10;
    int j = e & 1023;
    size_t base = (size_t)b * NG + j;

    float4 xf = *(const float4*)(xw + base);
    float4 xi = *(const float4*)(xw + base + 1024);
    float4 xg = *(const float4*)(xw + base + 2048);
    float4 xo = *(const float4*)(xw + base + 3072);
    float4 hf = __ldcg((const float4*)(g_hw + base));
    float4 hi_ = __ldcg((const float4*)(g_hw + base + 1024));
    float4 hg = __ldcg((const float4*)(g_hw + base + 2048));
    float4 ho = __ldcg((const float4*)(g_hw + base + 3072));
    float4 cp = *(const float4*)(g_c + e);

    float4 cn, hn;
    cell_one(xf.x, xi.x, xg.x, xo.x, hf.x, hi_.x, hg.x, ho.x, cp.x, cn.x, hn.x);
    cell_one(xf.y, xi.y, xg.y, xo.y, hf.y, hi_.y, hg.y, ho.y, cp.y, cn.y, hn.y);
    cell_one(xf.z, xi.z, xg.z, xo.z, hf.z, hi_.z, hg.z, ho.z, cp.z, cn.z, hn.z);
    cell_one(xf.w, xi.w, xg.w, xo.w, hf.w, hi_.w, hg.w, ho.w, cp.w, cn.w, hn.w);

    *(float4*)(g_c + e) = cn;
    *(float4*)(hout + e) = hn;
}

// ---------------- tail: hx = stacked[T-1], cx = g_c ----------------
__global__ void tail_kernel(const float* __restrict__ hlast,
                            float* __restrict__ out_h,
                            float* __restrict__ out_c) {
    int idx = blockIdx.x * 256 + threadIdx.x;
    if (idx < BH) {
        out_h[idx] = hlast[idx];
        out_c[idx] = g_c[idx];
    }
}

// ---------------- launch ----------------
extern "C" void kernel_launch(void* const* d_in, const int* in_sizes, int n_in,
                              void* d_out, int out_size) {
    const float* inputs = (const float*)d_in[0];
    const float* Wf = (const float*)d_in[1];
    const float* bf = (const float*)d_in[2];
    const float* Wi = (const float*)d_in[3];
    const float* bi = (const float*)d_in[4];
    const float* Wg = (const float*)d_in[5];
    const float* bg = (const float*)d_in[6];
    const float* Wo = (const float*)d_in[7];
    const float* bo = (const float*)d_in[8];
    float* out = (float*)d_out;

    (void)in_sizes; (void)n_in; (void)out_size;

    // 1) repack weights + bias
    repack_kernel<<<(KK * NG + 255) / 256, 256>>>(Wf, Wi, Wg, Wo, bf, bi, bg, bo);

    // 2) zero cell state + barriers
    init_kernel<<<(BH + 255) / 256, 256>>>();

    // 3) precompute all x-projections: [T*B, D] @ Wx + b  -> g_XW
    dim3 g1(NG / 32, (TT * BB) / 64);   // 128 x 512 CTAs
    xproj_kernel<<<g1, 128>>>(inputs);

    // 4) sequential recurrence, one fused kernel per step
    for (int t = 0; t < TT; t++) {
        const float* hprev = (t == 0) ? nullptr : out + (size_t)(t - 1) * BH;
        step_kernel<<<128, 128>>>(hprev, out + (size_t)t * BH, t);
    }

    // 5) hx, cx outputs
    tail_kernel<<<(BH + 255) / 256, 256>>>(out + (size_t)(TT - 1) * BH,
                                           out + (size_t)TT * BH,
                                           out + (size_t)TT * BH + BH);
}

// round 3
// speedup vs baseline: 1.6604x; 1.6604x over previous
#include <cuda_runtime.h>
#include <cstdint>
#include <cstddef>

// Problem dims
#define TT 512
#define BB 64
#define DD 1024
#define HH 1024
#define NG 4096              // 4*H (interleaved gate layout: n' = 4*j + gate)
#define KK 1024
#define BH (BB*HH)           // 65536
#define BG (BB*NG)           // 262144

typedef unsigned long long ull;

#define SPLAT(p64, v)   asm("mov.b64 %0, {%1, %1};" : "=l"(p64) : "f"(v))
#define UNPK(p64, lo, hi) asm("mov.b64 {%0, %1}, %2;" : "=f"(lo), "=f"(hi) : "l"(p64))
#define FMA2(acc, a, b) asm("fma.rn.f32x2 %0, %1, %2, %0;" : "+l"(acc) : "l"(a), "l"(b))

// -------- device scratch (no allocations allowed) --------
__device__ float g_Wx[KK * NG];                 // 16 MB, [k][n'] interleaved
__device__ float g_Wh[KK * NG];                 // 16 MB, [k][n'] interleaved
__device__ float g_ball[NG];                    // fused bias, interleaved
__device__ float g_XW[(size_t)TT * BB * NG];    // 512 MB precomputed x-projections
__device__ unsigned int g_bar[TT];              // per-step grid barriers

// ---------------- repack weights into interleaved layout + zero barriers ----------------
__global__ void repack_kernel(const float* __restrict__ Wf, const float* __restrict__ Wi,
                              const float* __restrict__ Wg, const float* __restrict__ Wo,
                              const float* __restrict__ bf, const float* __restrict__ bi,
                              const float* __restrict__ bg, const float* __restrict__ bo) {
    int idx = blockIdx.x * 256 + threadIdx.x;   // [0, KK*NG)
    int k = idx >> 12;                          // / 4096
    int n = idx & (NG - 1);
    int c = n >> 2;                             // hidden unit j
    int g = n & 3;                              // gate: 0=f 1=i 2=g 3=o
    const float* W = (g == 0) ? Wf : (g == 1) ? Wi : (g == 2) ? Wg : Wo;
    g_Wx[idx] = W[(size_t)k * HH + c];                 // rows [0, D)
    g_Wh[idx] = W[(size_t)(k + DD) * HH + c];          // rows [D, D+H)
    if (idx < NG) {
        const float* bv = (g == 0) ? bf : (g == 1) ? bi : (g == 2) ? bg : bo;
        g_ball[idx] = bv[c];
    }
    if (idx < TT) g_bar[idx] = 0u;
}

// ---------------- xproj: XW = inputs @ Wx + b ----------------
// CTA tile 64m x 128n, 256 threads, thread 8m x 4n (16 f32x2 FMA per k)
__global__ __launch_bounds__(256) void xproj_kernel(const float* __restrict__ inputs) {
    __shared__ float As[32][64];    // [k][m]
    __shared__ float Bs[32][128];   // [k][n]
    const int tid = threadIdx.x;
    const int n0 = blockIdx.x * 128;
    const int m0 = blockIdx.y * 64;
    const int ng = tid & 31;        // n = n0 + 4*ng
    const int mg = tid >> 5;        // m = m0 + 8*mg
    const float* A = inputs + (size_t)m0 * KK;

    ull acc[4][4];
#pragma unroll
    for (int p = 0; p < 4; p++)
#pragma unroll
        for (int q = 0; q < 4; q++) acc[p][q] = 0ull;

    float4 pa[2], pb[4];
#pragma unroll
    for (int it = 0; it < 2; it++) {
        int j = tid + it * 256;
        pa[it] = *(const float4*)(A + (size_t)(j & 63) * KK + 4 * (j >> 6));
    }
#pragma unroll
    for (int it = 0; it < 4; it++) {
        int j = tid + it * 256;
        pb[it] = *(const float4*)(g_Wx + (size_t)(j >> 5) * NG + n0 + 4 * (j & 31));
    }

    for (int k0 = 0; k0 < KK; k0 += 32) {
#pragma unroll
        for (int it = 0; it < 2; it++) {
            int j = tid + it * 256;
            int m = j & 63, kq = j >> 6;
            As[4 * kq + 0][m] = pa[it].x;
            As[4 * kq + 1][m] = pa[it].y;
            As[4 * kq + 2][m] = pa[it].z;
            As[4 * kq + 3][m] = pa[it].w;
        }
#pragma unroll
        for (int it = 0; it < 4; it++) {
            int j = tid + it * 256;
            *(float4*)&Bs[j >> 5][4 * (j & 31)] = pb[it];
        }
        __syncthreads();
        if (k0 + 32 < KK) {
#pragma unroll
            for (int it = 0; it < 2; it++) {
                int j = tid + it * 256;
                pa[it] = *(const float4*)(A + (size_t)(j & 63) * KK + (k0 + 32) + 4 * (j >> 6));
            }
#pragma unroll
            for (int it = 0; it < 4; it++) {
                int j = tid + it * 256;
                pb[it] = *(const float4*)(g_Wx + (size_t)(k0 + 32 + (j >> 5)) * NG + n0 + 4 * (j & 31));
            }
        }
#pragma unroll 8
        for (int k = 0; k < 32; k++) {
            ull a[4];
#pragma unroll
            for (int p = 0; p < 4; p++)
                a[p] = *(const ull*)&As[k][8 * mg + 2 * p];
            float4 bv = *(const float4*)&Bs[k][4 * ng];
            ull b0, b1, b2, b3;
            SPLAT(b0, bv.x); SPLAT(b1, bv.y); SPLAT(b2, bv.z); SPLAT(b3, bv.w);
#pragma unroll
            for (int p = 0; p < 4; p++) {
                FMA2(acc[p][0], a[p], b0);
                FMA2(acc[p][1], a[p], b1);
                FMA2(acc[p][2], a[p], b2);
                FMA2(acc[p][3], a[p], b3);
            }
        }
        __syncthreads();
    }

    float4 bb = *(const float4*)&g_ball[n0 + 4 * ng];
#pragma unroll
    for (int p = 0; p < 4; p++) {
        float4 r0, r1;
        UNPK(acc[p][0], r0.x, r1.x);
        UNPK(acc[p][1], r0.y, r1.y);
        UNPK(acc[p][2], r0.z, r1.z);
        UNPK(acc[p][3], r0.w, r1.w);
        r0.x += bb.x; r0.y += bb.y; r0.z += bb.z; r0.w += bb.w;
        r1.x += bb.x; r1.y += bb.y; r1.z += bb.z; r1.w += bb.w;
        int m = m0 + 8 * mg + 2 * p;
        *(float4*)(g_XW + (size_t)m * NG + n0 + 4 * ng) = r0;
        *(float4*)(g_XW + (size_t)(m + 1) * NG + n0 + 4 * ng) = r1;
    }
}

// ---------------- persistent recurrence ----------------
__device__ __forceinline__ float sigf(float x) { return 1.0f / (1.0f + __expf(-x)); }

// 128 CTAs x 256 threads; CTA owns n-tile [n0, n0+32) = hidden units [8*cta, 8*cta+8)
__global__ __launch_bounds__(256) void recur_kernel(float* __restrict__ out) {
    __shared__ float As[64][64];    // [k][m] h-tile
    __shared__ float Bs[64][32];    // [k][n] Wh tile
    __shared__ float hws[64][36];   // [b][n_local] gemm result (padded)

    const int tid = threadIdx.x;
    const int n0 = blockIdx.x * 32;
    const int ng = tid & 15;        // n pair: n_local = 2*ng
    const int mg = tid >> 4;        // m = 4*mg
    // cell assignment: 2 cells per thread
    const int ci = 2 * tid;
    const int cb = ci >> 3;         // batch b (0..63)
    const int cj = ci & 7;          // local j (even)
    const int jg = blockIdx.x * 8 + cj;

    float c0 = 0.0f, c1 = 0.0f;

    for (int t = 0; t < TT; t++) {
        if (t > 0) {
            const float* A = out + (size_t)(t - 1) * BH;   // h_{t-1}
            ull a00 = 0ull, a01 = 0ull, a10 = 0ull, a11 = 0ull;
            float4 pa[4], pb[2];
#pragma unroll
            for (int it = 0; it < 4; it++) {
                int j = tid + it * 256;
                pa[it] = *(const float4*)(A + (size_t)(j & 63) * HH + 4 * (j >> 6));
            }
#pragma unroll
            for (int it = 0; it < 2; it++) {
                int j = tid + it * 256;
                pb[it] = *(const float4*)(g_Wh + (size_t)(j >> 3) * NG + n0 + 4 * (j & 7));
            }
            for (int k0 = 0; k0 < KK; k0 += 64) {
#pragma unroll
                for (int it = 0; it < 4; it++) {
                    int j = tid + it * 256;
                    int m = j & 63, kq = j >> 6;
                    As[4 * kq + 0][m] = pa[it].x;
                    As[4 * kq + 1][m] = pa[it].y;
                    As[4 * kq + 2][m] = pa[it].z;
                    As[4 * kq + 3][m] = pa[it].w;
                }
#pragma unroll
                for (int it = 0; it < 2; it++) {
                    int j = tid + it * 256;
                    *(float4*)&Bs[j >> 3][4 * (j & 7)] = pb[it];
                }
                __syncthreads();
                if (k0 + 64 < KK) {
#pragma unroll
                    for (int it = 0; it < 4; it++) {
                        int j = tid + it * 256;
                        pa[it] = *(const float4*)(A + (size_t)(j & 63) * HH + (k0 + 64) + 4 * (j >> 6));
                    }
#pragma unroll
                    for (int it = 0; it < 2; it++) {
                        int j = tid + it * 256;
                        pb[it] = *(const float4*)(g_Wh + (size_t)(k0 + 64 + (j >> 3)) * NG + n0 + 4 * (j & 7));
                    }
                }
#pragma unroll 16
                for (int k = 0; k < 64; k++) {
                    ull av0 = *(const ull*)&As[k][4 * mg];
                    ull av1 = *(const ull*)&As[k][4 * mg + 2];
                    float2 bv = *(const float2*)&Bs[k][2 * ng];
                    ull b0, b1;
                    SPLAT(b0, bv.x); SPLAT(b1, bv.y);
                    FMA2(a00, av0, b0); FMA2(a01, av0, b1);
                    FMA2(a10, av1, b0); FMA2(a11, av1, b1);
                }
                __syncthreads();
            }
            float lo, hi;
            UNPK(a00, lo, hi); hws[4 * mg + 0][2 * ng] = lo;     hws[4 * mg + 1][2 * ng] = hi;
            UNPK(a01, lo, hi); hws[4 * mg + 0][2 * ng + 1] = lo; hws[4 * mg + 1][2 * ng + 1] = hi;
            UNPK(a10, lo, hi); hws[4 * mg + 2][2 * ng] = lo;     hws[4 * mg + 3][2 * ng] = hi;
            UNPK(a11, lo, hi); hws[4 * mg + 2][2 * ng + 1] = lo; hws[4 * mg + 3][2 * ng + 1] = hi;
        } else {
#pragma unroll
            for (int it = 0; it < 9; it++)
                (&hws[0][0])[tid + it * 256] = 0.0f;
        }
        __syncthreads();

        // ---- CTA-local cell update for 2 cells (b=cb, j=jg, jg+1) ----
        const float* xw = g_XW + (size_t)t * BG + (size_t)cb * NG + n0 + 4 * cj;
        float4 x0 = *(const float4*)xw;              // gates f,i,g,o for j=jg
        float4 x1 = *(const float4*)(xw + 4);        // gates for j=jg+1
        float4 h0 = *(const float4*)&hws[cb][4 * cj];
        float4 h1 = *(const float4*)&hws[cb][4 * cj + 4];

        float f0 = sigf(x0.x + h0.x), i0 = sigf(x0.y + h0.y);
        float gg0 = tanhf(x0.z + h0.z), o0 = sigf(x0.w + h0.w);
        c0 = f0 * c0 + i0 * gg0;
        float hn0 = o0 * tanhf(c0);

        float f1 = sigf(x1.x + h1.x), i1 = sigf(x1.y + h1.y);
        float gg1 = tanhf(x1.z + h1.z), o1 = sigf(x1.w + h1.w);
        c1 = f1 * c1 + i1 * gg1;
        float hn1 = o1 * tanhf(c1);

        float* orow = out + (size_t)t * BH + (size_t)cb * HH + jg;
        orow[0] = hn0;
        orow[1] = hn1;

        if (t == TT - 1) {
            float* hx = out + (size_t)TT * BH + (size_t)cb * HH + jg;
            hx[0] = hn0; hx[1] = hn1;
            float* cx = hx + BH;
            cx[0] = c0;  cx[1] = c1;
        } else {
            // ---- device-wide barrier: h_t visible to all CTAs ----
            __syncthreads();
            if (tid == 0) {
                __threadfence();
                atomicAdd(&g_bar[t], 1u);
                while (*((volatile unsigned int*)&g_bar[t]) < 128u) { }
                __threadfence();
            }
            __syncthreads();
        }
    }
}

// ---------------- launch ----------------
extern "C" void kernel_launch(void* const* d_in, const int* in_sizes, int n_in,
                              void* d_out, int out_size) {
    const float* inputs = (const float*)d_in[0];
    const float* Wf = (const float*)d_in[1];
    const float* bf = (const float*)d_in[2];
    const float* Wi = (const float*)d_in[3];
    const float* bi = (const float*)d_in[4];
    const float* Wg = (const float*)d_in[5];
    const float* bg = (const float*)d_in[6];
    const float* Wo = (const float*)d_in[7];
    const float* bo = (const float*)d_in[8];
    float* out = (float*)d_out;
    (void)in_sizes; (void)n_in; (void)out_size;

    // 1) repack weights into interleaved layout + zero barriers
    repack_kernel<<<(KK * NG) / 256, 256>>>(Wf, Wi, Wg, Wo, bf, bi, bg, bo);

    // 2) precompute all x-projections (+bias), interleaved layout
    xproj_kernel<<<dim3(NG / 128, (TT * BB) / 64), 256>>>(inputs);

    // 3) persistent recurrence: one kernel, 512 steps, 1 grid barrier per step
    recur_kernel<<<128, 256>>>(out);
}

// round 11
// speedup vs baseline: 2.6838x; 1.6164x over previous
#include <cuda_runtime.h>
#include <cuda_bf16.h>
#include <cstdint>
#include <cstddef>

// Problem dims
#define TT 512
#define BB 64
#define HH 1024
#define NG 4096              // 4*H, gate-interleaved: m (= n') = 4*j + gate(f,i,g,o)
#define KK 1024
#define KK2 2048             // stored K for recurrence W/h: [hi | lo]
#define BH (BB*HH)
#define BG (BB*NG)

typedef __nv_bfloat16 bf16;
typedef unsigned long long ull;

#define SPLAT(p64, v)   asm("mov.b64 %0, {%1, %1};" : "=l"(p64) : "f"(v))
#define UNPK(p64, lo, hi) asm("mov.b64 {%0, %1}, %2;" : "=f"(lo), "=f"(hi) : "l"(p64))
#define FMA2(acc, a, b) asm("fma.rn.f32x2 %0, %1, %2, %0;" : "+l"(acc) : "l"(a), "l"(b))

// -------- device scratch (no allocations allowed) --------
__device__ float g_Wx[KK * NG];                       // fp32 [k][n'] for xproj (round-3 layout)
__device__ __align__(16) bf16 g_Wh2[(size_t)NG * KK2]; // bf16 split [m][hi|lo] for recurrence
__device__ __align__(16) bf16 g_h2[2][BB * KK2];       // double-buffered h splits [b][hi|lo]
__device__ float g_ball[NG];
__device__ float g_XW[(size_t)TT * BB * NG];
__device__ unsigned int g_bar[TT];

// ---------------- low-level helpers (sm_80+ only) ----------------
__device__ __forceinline__ uint32_t smem_u32(const void* p) {
    uint32_t a;
    asm("{ .reg .u64 t; cvta.to.shared.u64 t, %1; cvt.u32.u64 %0, t; }" : "=r"(a) : "l"(p));
    return a;
}
__device__ __forceinline__ void cp16(uint32_t dst, const void* src) {
    asm volatile("cp.async.cg.shared.global [%0], [%1], 16;" :: "r"(dst), "l"(src) : "memory");
}
#define CP_COMMIT() asm volatile("cp.async.commit_group;" ::: "memory")
#define CP_WAIT1()  asm volatile("cp.async.wait_group 1;" ::: "memory")
#define CP_WAIT0()  asm volatile("cp.async.wait_group 0;" ::: "memory")

__device__ __forceinline__ uint32_t lds32(uint32_t a) {
    uint32_t v; asm volatile("ld.shared.b32 %0, [%1];" : "=r"(v) : "r"(a)); return v;
}
__device__ __forceinline__ float lds_f32(uint32_t a) {
    float v; asm volatile("ld.shared.f32 %0, [%1];" : "=f"(v) : "r"(a)); return v;
}
__device__ __forceinline__ void sts128(uint32_t a, uint4 v) {
    asm volatile("st.shared.v4.b32 [%0], {%1,%2,%3,%4};" :: "r"(a), "r"(v.x), "r"(v.y), "r"(v.z), "r"(v.w) : "memory");
}
__device__ __forceinline__ void sts_f32(uint32_t a, float v) {
    asm volatile("st.shared.f32 [%0], %1;" :: "r"(a), "f"(v) : "memory");
}
__device__ __forceinline__ void mma16816(float* c,
                                         uint32_t a0, uint32_t a1, uint32_t a2, uint32_t a3,
                                         uint32_t b0, uint32_t b1) {
    asm volatile(
        "mma.sync.aligned.m16n8k16.row.col.f32.bf16.bf16.f32 "
        "{%0,%1,%2,%3}, {%4,%5,%6,%7}, {%8,%9}, {%0,%1,%2,%3};"
        : "+f"(c[0]), "+f"(c[1]), "+f"(c[2]), "+f"(c[3])
        : "r"(a0), "r"(a1), "r"(a2), "r"(a3), "r"(b0), "r"(b1));
}

// ---------------- prep kernel ----------------
__global__ void repack_kernel(const float* __restrict__ Wf, const float* __restrict__ Wi,
                              const float* __restrict__ Wg, const float* __restrict__ Wo,
                              const float* __restrict__ bf_, const float* __restrict__ bi_,
                              const float* __restrict__ bg_, const float* __restrict__ bo_) {
    int idx = blockIdx.x * 256 + threadIdx.x;   // idx = k*NG + n   (round-3 convention)
    int k = idx >> 12;
    int n = idx & (NG - 1);
    int c = n >> 2, g = n & 3;
    const float* W = (g == 0) ? Wf : (g == 1) ? Wi : (g == 2) ? Wg : Wo;
    float wx = W[(size_t)k * HH + c];
    float wh = W[(size_t)(k + 1024) * HH + c];
    g_Wx[idx] = wx;                                   // fp32 [k][n'] for xproj
    bf16 hh = __float2bfloat16(wh);                   // bf16 split [n'=m][k] for recurrence
    g_Wh2[(size_t)n * KK2 + k]        = hh;
    g_Wh2[(size_t)n * KK2 + 1024 + k] = __float2bfloat16(wh - __bfloat162float(hh));
    if (idx < NG) {
        const float* bv = (g == 0) ? bf_ : (g == 1) ? bi_ : (g == 2) ? bg_ : bo_;
        g_ball[idx] = bv[c];
    }
    if (idx < TT) g_bar[idx] = 0u;
}

// ================= xproj: VERBATIM round-3 fp32 f32x2 GEMM (verified correct) =================
// CTA tile 64m x 128n, 256 threads, thread 8m x 4n (16 f32x2 FMA per k)
__global__ __launch_bounds__(256) void xproj_kernel(const float* __restrict__ inputs) {
    __shared__ float As[32][64];    // [k][m]
    __shared__ float Bs[32][128];   // [k][n]
    const int tid = threadIdx.x;
    const int n0 = blockIdx.x * 128;
    const int m0 = blockIdx.y * 64;
    const int ng = tid & 31;        // n = n0 + 4*ng
    const int mg = tid >> 5;        // m = m0 + 8*mg
    const float* A = inputs + (size_t)m0 * KK;

    ull acc[4][4];
#pragma unroll
    for (int p = 0; p < 4; p++)
#pragma unroll
        for (int q = 0; q < 4; q++) acc[p][q] = 0ull;

    float4 pa[2], pb[4];
#pragma unroll
    for (int it = 0; it < 2; it++) {
        int j = tid + it * 256;
        pa[it] = *(const float4*)(A + (size_t)(j & 63) * KK + 4 * (j >> 6));
    }
#pragma unroll
    for (int it = 0; it < 4; it++) {
        int j = tid + it * 256;
        pb[it] = *(const float4*)(g_Wx + (size_t)(j >> 5) * NG + n0 + 4 * (j & 31));
    }

    for (int k0 = 0; k0 < KK; k0 += 32) {
#pragma unroll
        for (int it = 0; it < 2; it++) {
            int j = tid + it * 256;
            int m = j & 63, kq = j >> 6;
            As[4 * kq + 0][m] = pa[it].x;
            As[4 * kq + 1][m] = pa[it].y;
            As[4 * kq + 2][m] = pa[it].z;
            As[4 * kq + 3][m] = pa[it].w;
        }
#pragma unroll
        for (int it = 0; it < 4; it++) {
            int j = tid + it * 256;
            *(float4*)&Bs[j >> 5][4 * (j & 31)] = pb[it];
        }
        __syncthreads();
        if (k0 + 32 < KK) {
#pragma unroll
            for (int it = 0; it < 2; it++) {
                int j = tid + it * 256;
                pa[it] = *(const float4*)(A + (size_t)(j & 63) * KK + (k0 + 32) + 4 * (j >> 6));
            }
#pragma unroll
            for (int it = 0; it < 4; it++) {
                int j = tid + it * 256;
                pb[it] = *(const float4*)(g_Wx + (size_t)(k0 + 32 + (j >> 5)) * NG + n0 + 4 * (j & 31));
            }
        }
#pragma unroll 8
        for (int k = 0; k < 32; k++) {
            ull a[4];
#pragma unroll
            for (int p = 0; p < 4; p++)
                a[p] = *(const ull*)&As[k][8 * mg + 2 * p];
            float4 bv = *(const float4*)&Bs[k][4 * ng];
            ull b0, b1, b2, b3;
            SPLAT(b0, bv.x); SPLAT(b1, bv.y); SPLAT(b2, bv.z); SPLAT(b3, bv.w);
#pragma unroll
            for (int p = 0; p < 4; p++) {
                FMA2(acc[p][0], a[p], b0);
                FMA2(acc[p][1], a[p], b1);
                FMA2(acc[p][2], a[p], b2);
                FMA2(acc[p][3], a[p], b3);
            }
        }
        __syncthreads();
    }

    float4 bb = *(const float4*)&g_ball[n0 + 4 * ng];
#pragma unroll
    for (int p = 0; p < 4; p++) {
        float4 r0, r1;
        UNPK(acc[p][0], r0.x, r1.x);
        UNPK(acc[p][1], r0.y, r1.y);
        UNPK(acc[p][2], r0.z, r1.z);
        UNPK(acc[p][3], r0.w, r1.w);
        r0.x += bb.x; r0.y += bb.y; r0.z += bb.z; r0.w += bb.w;
        r1.x += bb.x; r1.y += bb.y; r1.z += bb.z; r1.w += bb.w;
        int m = m0 + 8 * mg + 2 * p;
        *(float4*)(g_XW + (size_t)m * NG + n0 + 4 * ng) = r0;
        *(float4*)(g_XW + (size_t)(m + 1) * NG + n0 + 4 * ng) = r1;
    }
}

// ================= persistent recurrence (round-9 mma, virtual K'' = 3072) =================
#define R_PW  2056                     // W smem pitch (bf16): 4112B/row
#define R_WB  (32 * R_PW * 2)          // 131584
#define R_P   264                      // h smem pitch (bf16): 528B/row
#define R_TB  (64 * R_P * 2)           // 33792 per buffer
#define R_DOF (R_WB + 2 * R_TB)        // 199168
#define R_SMEM (R_DOF + 32 * 65 * 4)   // 207488

__device__ __forceinline__ void recur_issueB(uint32_t sb, int tid, int ck, int par) {
    uint32_t base = sb + R_WB + (uint32_t)(ck & 1) * R_TB;
    // B = [hhi | hlo] : segs hi(ck<4), hi(4<=ck<8), lo(ck>=8)
    int kb = (ck < 4) ? ck * 256 : (ck - 4) * 256;
#pragma unroll
    for (int it = 0; it < 8; ++it) {
        int j = tid + it * 256;            // 0..2047 16B-units
        int n = j >> 5, kq = j & 31;
        uint32_t d = base + (uint32_t)(n * R_P + kq * 8) * 2;
        cp16(d, g_h2[par] + (size_t)n * KK2 + kb + kq * 8);
    }
    CP_COMMIT();
}

__device__ __forceinline__ float sigf(float x) { return 1.0f / (1.0f + __expf(-x)); }

__device__ __forceinline__ void grid_barrier(int t) {
    __syncthreads();
    if (threadIdx.x == 0) {
        __threadfence();
        atomicAdd(&g_bar[t], 1u);
        while (*((volatile unsigned int*)&g_bar[t]) < 128u) { __nanosleep(32); }
        __threadfence();
    }
    __syncthreads();
}

__global__ __launch_bounds__(256) void recur_kernel(float* __restrict__ out) {
    extern __shared__ __align__(16) char smem[];
    uint32_t sb = smem_u32(smem);
    const int tid = threadIdx.x;
    const int w = tid >> 5, lane = tid & 31;
    const int g = lane >> 2, c4 = lane & 3;
    const int m0 = blockIdx.x * 32;     // gate-row base
    const int j0 = blockIdx.x * 8;      // hidden-unit base
    const int mg = w & 1, ngp = w >> 1; // warp tile: m16 x n16

    // ---- load this CTA's W [hi|lo] slice into SMEM once ----
#pragma unroll
    for (int it = 0; it < 32; ++it) {
        int j = tid + it * 256;             // 0..8191 16B-units
        int r = j >> 8, kq = j & 255;
        uint32_t off = (uint32_t)(r * R_PW + kq * 8) * 2;
        uint4 v = *(const uint4*)(g_Wh2 + (size_t)(m0 + r) * KK2 + kq * 8);
        sts128(sb + off, v);
    }
    __syncthreads();

    // ---- t = 0 (h_{-1} = 0): write h_0 splits into buffer 0 ----
    float cc[2];
#pragma unroll
    for (int q = 0; q < 2; ++q) {
        int e = tid + q * 256;
        int u = e >> 6, b = e & 63;
        float4 xw = *(const float4*)(g_XW + (size_t)b * NG + m0 + 4 * u);
        float i = sigf(xw.y), gg = tanhf(xw.z), o = sigf(xw.w);
        cc[q] = i * gg;
        float h = o * tanhf(cc[q]);
        out[(size_t)b * HH + j0 + u] = h;
        bf16 hh = __float2bfloat16(h);
        g_h2[0][b * KK2 + j0 + u]        = hh;
        g_h2[0][b * KK2 + 1024 + j0 + u] = __float2bfloat16(h - __bfloat162float(hh));
    }
    grid_barrier(0);

    const uint32_t dbase = sb + R_DOF;
    for (int t = 1; t < TT; ++t) {
        const int rpar = (t - 1) & 1;
        const int wpar = t & 1;
        float acc[2][4] = {{0.f, 0.f, 0.f, 0.f}, {0.f, 0.f, 0.f, 0.f}};
        recur_issueB(sb, tid, 0, rpar);
        for (int ck = 0; ck < 12; ++ck) {
            if (ck < 11) { recur_issueB(sb, tid, ck + 1, rpar); CP_WAIT1(); }
            else CP_WAIT0();
            __syncthreads();
            uint32_t bb = sb + R_WB + (uint32_t)(ck & 1) * R_TB;
            // A = W smem [hi|lo] : segs hi(ck<4), lo(4<=ck<8), hi(ck>=8)
            int kwb = (ck < 8) ? ck * 256 : (ck - 8) * 256;
#pragma unroll
            for (int kk = 0; kk < 16; ++kk) {
                int kbw = kwb + kk * 16;
                int kbb = kk * 16;
                int r0 = 16 * mg + g;
                uint32_t o0 = sb + (uint32_t)(r0 * R_PW + kbw + 2 * c4) * 2;
                uint32_t o1 = o0 + 8 * R_PW * 2;
                uint32_t a0 = lds32(o0),      a1 = lds32(o1);
                uint32_t a2 = lds32(o0 + 16), a3 = lds32(o1 + 16);
#pragma unroll
                for (int s = 0; s < 2; ++s) {
                    int nr = 16 * ngp + 8 * s + g;
                    uint32_t ob = bb + (uint32_t)(nr * R_P + kbb + 2 * c4) * 2;
                    uint32_t b0 = lds32(ob), b1 = lds32(ob + 16);
                    mma16816(acc[s], a0, a1, a2, a3, b0, b1);
                }
            }
            __syncthreads();
        }
        // ---- stage D into SMEM ----
#pragma unroll
        for (int s = 0; s < 2; ++s) {
            int r = 16 * mg + g;
            int nb = 16 * ngp + 8 * s + 2 * c4;
            sts_f32(dbase + (uint32_t)(r * 65 + nb) * 4,           acc[s][0]);
            sts_f32(dbase + (uint32_t)(r * 65 + nb + 1) * 4,       acc[s][1]);
            sts_f32(dbase + (uint32_t)((r + 8) * 65 + nb) * 4,     acc[s][2]);
            sts_f32(dbase + (uint32_t)((r + 8) * 65 + nb + 1) * 4, acc[s][3]);
        }
        __syncthreads();
        // ---- cell update (2 cells per thread) ----
#pragma unroll
        for (int q = 0; q < 2; ++q) {
            int e = tid + q * 256;
            int u = e >> 6, b = e & 63;
            float4 xw = *(const float4*)(g_XW + (size_t)t * BG + (size_t)b * NG + m0 + 4 * u);
            float hf  = lds_f32(dbase + (uint32_t)((4 * u + 0) * 65 + b) * 4);
            float hi_ = lds_f32(dbase + (uint32_t)((4 * u + 1) * 65 + b) * 4);
            float hg  = lds_f32(dbase + (uint32_t)((4 * u + 2) * 65 + b) * 4);
            float ho  = lds_f32(dbase + (uint32_t)((4 * u + 3) * 65 + b) * 4);
            float f  = sigf(xw.x + hf);
            float i  = sigf(xw.y + hi_);
            float gg = tanhf(xw.z + hg);
            float o  = sigf(xw.w + ho);
            cc[q] = f * cc[q] + i * gg;
            float h = o * tanhf(cc[q]);
            out[(size_t)t * BH + (size_t)b * HH + j0 + u] = h;
            bf16 hh = __float2bfloat16(h);
            g_h2[wpar][b * KK2 + j0 + u]        = hh;
            g_h2[wpar][b * KK2 + 1024 + j0 + u] = __float2bfloat16(h - __bfloat162float(hh));
            if (t == TT - 1) {
                out[(size_t)TT * BH + (size_t)b * HH + j0 + u] = h;            // hx
                out[(size_t)TT * BH + BH + (size_t)b * HH + j0 + u] = cc[q];   // cx
            }
        }
        if (t < TT - 1) grid_barrier(t);
    }
}

// ---------------- launch ----------------
extern "C" void kernel_launch(void* const* d_in, const int* in_sizes, int n_in,
                              void* d_out, int out_size) {
    const float* inputs = (const float*)d_in[0];
    const float* Wf = (const float*)d_in[1];
    const float* bf_ = (const float*)d_in[2];
    const float* Wi = (const float*)d_in[3];
    const float* bi_ = (const float*)d_in[4];
    const float* Wg = (const float*)d_in[5];
    const float* bg_ = (const float*)d_in[6];
    const float* Wo = (const float*)d_in[7];
    const float* bo_ = (const float*)d_in[8];
    float* out = (float*)d_out;
    (void)in_sizes; (void)n_in; (void)out_size;

    cudaFuncSetAttribute(recur_kernel, cudaFuncAttributeMaxDynamicSharedMemorySize, R_SMEM);

    // 1) repack: fp32 [k][n'] for xproj + bf16 split [m][k] for recurrence
    repack_kernel<<<(KK * NG) / 256, 256>>>(Wf, Wi, Wg, Wo, bf_, bi_, bg_, bo_);

    // 2) x-projections: VERIFIED round-3 fp32 f32x2 GEMM
    xproj_kernel<<<dim3(NG / 128, (TT * BB) / 64), 256>>>(inputs);

    // 3) persistent recurrence: round-9 mma bf16-split (under test)
    recur_kernel<<<128, 256, R_SMEM>>>(out);
}

// round 12
// speedup vs baseline: 3.4924x; 1.3013x over previous
#include <cuda_runtime.h>
#include <cuda_bf16.h>
#include <cstdint>
#include <cstddef>

// Problem dims
#define TT 512
#define BB 64
#define HH 1024
#define NG 4096              // 4*H, gate-interleaved: m (= n') = 4*j + gate(f,i,g,o)
#define KK 1024
#define KK2 2048             // stored K: [hi | lo]
#define BH (BB*HH)
#define BG (BB*NG)

typedef __nv_bfloat16 bf16;

// -------- device scratch (no allocations allowed) --------
__device__ __align__(16) bf16 g_Wx2[(size_t)NG * KK2]; // [m][hi|lo] for xproj
__device__ __align__(16) bf16 g_Wh2[(size_t)NG * KK2]; // [m][hi|lo] for recurrence
__device__ __align__(16) bf16 g_X2[(size_t)TT * BB * KK2]; // [s][hi|lo]
__device__ __align__(16) bf16 g_h2[2][BB * KK2];       // double-buffered h splits [b][hi|lo]
__device__ float g_ball[NG];
__device__ float g_XW[(size_t)TT * BB * NG];
__device__ unsigned int g_bar[TT];

// ---------------- low-level helpers (sm_80+ only) ----------------
__device__ __forceinline__ uint32_t smem_u32(const void* p) {
    uint32_t a;
    asm("{ .reg .u64 t; cvta.to.shared.u64 t, %1; cvt.u32.u64 %0, t; }" : "=r"(a) : "l"(p));
    return a;
}
__device__ __forceinline__ void cp16(uint32_t dst, const void* src) {
    asm volatile("cp.async.cg.shared.global [%0], [%1], 16;" :: "r"(dst), "l"(src) : "memory");
}
#define CP_COMMIT() asm volatile("cp.async.commit_group;" ::: "memory")
#define CP_WAIT1()  asm volatile("cp.async.wait_group 1;" ::: "memory")
#define CP_WAIT0()  asm volatile("cp.async.wait_group 0;" ::: "memory")

__device__ __forceinline__ uint32_t lds32(uint32_t a) {
    uint32_t v; asm volatile("ld.shared.b32 %0, [%1];" : "=r"(v) : "r"(a)); return v;
}
__device__ __forceinline__ float lds_f32(uint32_t a) {
    float v; asm volatile("ld.shared.f32 %0, [%1];" : "=f"(v) : "r"(a)); return v;
}
__device__ __forceinline__ void sts128(uint32_t a, uint4 v) {
    asm volatile("st.shared.v4.b32 [%0], {%1,%2,%3,%4};" :: "r"(a), "r"(v.x), "r"(v.y), "r"(v.z), "r"(v.w) : "memory");
}
__device__ __forceinline__ void sts_f32(uint32_t a, float v) {
    asm volatile("st.shared.f32 [%0], %1;" :: "r"(a), "f"(v) : "memory");
}
__device__ __forceinline__ void mma16816(float* c,
                                         uint32_t a0, uint32_t a1, uint32_t a2, uint32_t a3,
                                         uint32_t b0, uint32_t b1) {
    asm volatile(
        "mma.sync.aligned.m16n8k16.row.col.f32.bf16.bf16.f32 "
        "{%0,%1,%2,%3}, {%4,%5,%6,%7}, {%8,%9}, {%0,%1,%2,%3};"
        : "+f"(c[0]), "+f"(c[1]), "+f"(c[2]), "+f"(c[3])
        : "r"(a0), "r"(a1), "r"(a2), "r"(a3), "r"(b0), "r"(b1));
}

// ---------------- prep kernels ----------------
// K-MAJOR index convention (idx = k*NG + n) — the bias guard `idx < NG` is only
// correct in this convention (idx<NG <=> k=0, n=idx). The m-major variant of
// this kernel silently corrupted g_ball (root cause of the 8.4e-2 failures).
__global__ void repack_kernel(const float* __restrict__ Wf, const float* __restrict__ Wi,
                              const float* __restrict__ Wg, const float* __restrict__ Wo,
                              const float* __restrict__ bf_, const float* __restrict__ bi_,
                              const float* __restrict__ bg_, const float* __restrict__ bo_) {
    int idx = blockIdx.x * 256 + threadIdx.x;   // idx = k*NG + n
    int k = idx >> 12;
    int n = idx & (NG - 1);
    int c = n >> 2, g = n & 3;
    const float* W = (g == 0) ? Wf : (g == 1) ? Wi : (g == 2) ? Wg : Wo;
    float wx = W[(size_t)k * HH + c];
    float wh = W[(size_t)(k + 1024) * HH + c];
    bf16 xh = __float2bfloat16(wx);
    g_Wx2[(size_t)n * KK2 + k]        = xh;
    g_Wx2[(size_t)n * KK2 + 1024 + k] = __float2bfloat16(wx - __bfloat162float(xh));
    bf16 hh = __float2bfloat16(wh);
    g_Wh2[(size_t)n * KK2 + k]        = hh;
    g_Wh2[(size_t)n * KK2 + 1024 + k] = __float2bfloat16(wh - __bfloat162float(hh));
    if (idx < NG) {
        const float* bv = (g == 0) ? bf_ : (g == 1) ? bi_ : (g == 2) ? bg_ : bo_;
        g_ball[idx] = bv[c];
    }
    if (idx < TT) g_bar[idx] = 0u;
}

__global__ void convx_kernel(const float* __restrict__ inp) {
    int idx = blockIdx.x * 256 + threadIdx.x;   // s*1024 + k
    int s = idx >> 10, k = idx & 1023;
    float v = inp[idx];
    bf16 h = __float2bfloat16(v);
    g_X2[(size_t)s * KK2 + k]        = h;
    g_X2[(size_t)s * KK2 + 1024 + k] = __float2bfloat16(v - __bfloat162float(h));
}

// ================= xproj: virtual K'' = 3072 plain bf16 GEMM (round-9 core) =================
// CTA tile M128 x N128, chunk 128 k'', 24 chunks, double-buffered cp.async.
// Per-chunk source remap realizes  Whi*Xhi + Wlo*Xhi + Whi*Xlo.
#define X_P   136                      // smem pitch (bf16)
#define X_TB  (128 * X_P * 2)          // 34816 B per tile buffer
#define X_SMEM (4 * X_TB)              // A0,A1,B0,B1 = 139264

__device__ __forceinline__ void xp_issue(uint32_t sb, int tid, int ck, int m0, int n0) {
    uint32_t ab = sb + (uint32_t)(ck & 1) * X_TB;
    uint32_t bb = sb + 2 * X_TB + (uint32_t)(ck & 1) * X_TB;
    // A = [Whi | Wlo] : segs hi(ck<8), lo(8<=ck<16), hi(ck>=16)
    int ka = (ck < 16) ? ck * 128 : (ck - 16) * 128;
    // B = [Xhi | Xlo] : segs hi, hi, lo
    int kb = (ck < 8) ? ck * 128 : (ck - 8) * 128;
#pragma unroll
    for (int it = 0; it < 8; ++it) {
        int j = tid + it * 256;            // 0..2047 16B-units
        int r = j >> 4, kq = j & 15;
        uint32_t off = (uint32_t)(r * X_P + kq * 8) * 2;
        cp16(ab + off, g_Wx2 + (size_t)(m0 + r) * KK2 + ka + kq * 8);
        cp16(bb + off, g_X2 + (size_t)(n0 + r) * KK2 + kb + kq * 8);
    }
    CP_COMMIT();
}

__global__ __launch_bounds__(256) void xproj_kernel() {
    extern __shared__ __align__(16) char smem[];
    uint32_t sb = smem_u32(smem);
    const int tid = threadIdx.x;
    const int w = tid >> 5, lane = tid & 31;
    const int g = lane >> 2, c4 = lane & 3;
    const int m0 = blockIdx.x * 128, n0 = blockIdx.y * 128;
    const int mg = w >> 1, ngp = w & 1;     // warp tile: m32 x n64

    float acc[2][8][4];
#pragma unroll
    for (int a = 0; a < 2; ++a)
#pragma unroll
        for (int b = 0; b < 8; ++b)
#pragma unroll
            for (int d = 0; d < 4; ++d) acc[a][b][d] = 0.f;

    xp_issue(sb, tid, 0, m0, n0);
    for (int ck = 0; ck < 24; ++ck) {
        if (ck < 23) { xp_issue(sb, tid, ck + 1, m0, n0); CP_WAIT1(); }
        else CP_WAIT0();
        __syncthreads();
        uint32_t ab = sb + (uint32_t)(ck & 1) * X_TB;
        uint32_t bb = sb + 2 * X_TB + (uint32_t)(ck & 1) * X_TB;
#pragma unroll
        for (int kk = 0; kk < 8; ++kk) {
            int kb = kk * 16;
            uint32_t a0[2], a1[2], a2[2], a3[2];
#pragma unroll
            for (int mt = 0; mt < 2; ++mt) {
                int r0 = 32 * mg + 16 * mt + g;
                uint32_t o0 = ab + (uint32_t)(r0 * X_P + kb + 2 * c4) * 2;
                uint32_t o1 = o0 + 8 * X_P * 2;
                a0[mt] = lds32(o0);      a1[mt] = lds32(o1);
                a2[mt] = lds32(o0 + 16); a3[mt] = lds32(o1 + 16);
            }
#pragma unroll
            for (int nt = 0; nt < 8; ++nt) {
                int nr = 64 * ngp + 8 * nt + g;
                uint32_t ob = bb + (uint32_t)(nr * X_P + kb + 2 * c4) * 2;
                uint32_t b0 = lds32(ob), b1 = lds32(ob + 16);
#pragma unroll
                for (int mt = 0; mt < 2; ++mt)
                    mma16816(acc[mt][nt], a0[mt], a1[mt], a2[mt], a3[mt], b0, b1);
            }
        }
        __syncthreads();
    }
    // epilogue: D[m][n] + bias -> g_XW[n][m]
#pragma unroll
    for (int mt = 0; mt < 2; ++mt) {
        int mrow = m0 + 32 * mg + 16 * mt + g;
        float bv0 = g_ball[mrow], bv1 = g_ball[mrow + 8];
#pragma unroll
        for (int nt = 0; nt < 8; ++nt) {
            int nrow = n0 + 64 * ngp + 8 * nt + 2 * c4;
            g_XW[(size_t)nrow * NG + mrow]           = acc[mt][nt][0] + bv0;
            g_XW[(size_t)(nrow + 1) * NG + mrow]     = acc[mt][nt][1] + bv0;
            g_XW[(size_t)nrow * NG + mrow + 8]       = acc[mt][nt][2] + bv1;
            g_XW[(size_t)(nrow + 1) * NG + mrow + 8] = acc[mt][nt][3] + bv1;
        }
    }
}

// ================= persistent recurrence (round-11 verbatim, virtual K'' = 3072) =================
#define R_PW  2056                     // W smem pitch (bf16): 4112B/row
#define R_WB  (32 * R_PW * 2)          // 131584
#define R_P   264                      // h smem pitch (bf16): 528B/row
#define R_TB  (64 * R_P * 2)           // 33792 per buffer
#define R_DOF (R_WB + 2 * R_TB)        // 199168
#define R_SMEM (R_DOF + 32 * 65 * 4)   // 207488

__device__ __forceinline__ void recur_issueB(uint32_t sb, int tid, int ck, int par) {
    uint32_t base = sb + R_WB + (uint32_t)(ck & 1) * R_TB;
    // B = [hhi | hlo] : segs hi(ck<4), hi(4<=ck<8), lo(ck>=8)
    int kb = (ck < 4) ? ck * 256 : (ck - 4) * 256;
#pragma unroll
    for (int it = 0; it < 8; ++it) {
        int j = tid + it * 256;            // 0..2047 16B-units
        int n = j >> 5, kq = j & 31;
        uint32_t d = base + (uint32_t)(n * R_P + kq * 8) * 2;
        cp16(d, g_h2[par] + (size_t)n * KK2 + kb + kq * 8);
    }
    CP_COMMIT();
}

__device__ __forceinline__ float sigf(float x) { return 1.0f / (1.0f + __expf(-x)); }

__device__ __forceinline__ void grid_barrier(int t) {
    __syncthreads();
    if (threadIdx.x == 0) {
        __threadfence();
        atomicAdd(&g_bar[t], 1u);
        while (*((volatile unsigned int*)&g_bar[t]) < 128u) { __nanosleep(32); }
        __threadfence();
    }
    __syncthreads();
}

__global__ __launch_bounds__(256) void recur_kernel(float* __restrict__ out) {
    extern __shared__ __align__(16) char smem[];
    uint32_t sb = smem_u32(smem);
    const int tid = threadIdx.x;
    const int w = tid >> 5, lane = tid & 31;
    const int g = lane >> 2, c4 = lane & 3;
    const int m0 = blockIdx.x * 32;     // gate-row base
    const int j0 = blockIdx.x * 8;      // hidden-unit base
    const int mg = w & 1, ngp = w >> 1; // warp tile: m16 x n16

    // ---- load this CTA's W [hi|lo] slice into SMEM once ----
#pragma unroll
    for (int it = 0; it < 32; ++it) {
        int j = tid + it * 256;             // 0..8191 16B-units
        int r = j >> 8, kq = j & 255;
        uint32_t off = (uint32_t)(r * R_PW + kq * 8) * 2;
        uint4 v = *(const uint4*)(g_Wh2 + (size_t)(m0 + r) * KK2 + kq * 8);
        sts128(sb + off, v);
    }
    __syncthreads();

    // ---- t = 0 (h_{-1} = 0): write h_0 splits into buffer 0 ----
    float cc[2];
#pragma unroll
    for (int q = 0; q < 2; ++q) {
        int e = tid + q * 256;
        int u = e >> 6, b = e & 63;
        float4 xw = *(const float4*)(g_XW + (size_t)b * NG + m0 + 4 * u);
        float i = sigf(xw.y), gg = tanhf(xw.z), o = sigf(xw.w);
        cc[q] = i * gg;
        float h = o * tanhf(cc[q]);
        out[(size_t)b * HH + j0 + u] = h;
        bf16 hh = __float2bfloat16(h);
        g_h2[0][b * KK2 + j0 + u]        = hh;
        g_h2[0][b * KK2 + 1024 + j0 + u] = __float2bfloat16(h - __bfloat162float(hh));
    }
    grid_barrier(0);

    const uint32_t dbase = sb + R_DOF;
    for (int t = 1; t < TT; ++t) {
        const int rpar = (t - 1) & 1;
        const int wpar = t & 1;
        float acc[2][4] = {{0.f, 0.f, 0.f, 0.f}, {0.f, 0.f, 0.f, 0.f}};
        recur_issueB(sb, tid, 0, rpar);
        for (int ck = 0; ck < 12; ++ck) {
            if (ck < 11) { recur_issueB(sb, tid, ck + 1, rpar); CP_WAIT1(); }
            else CP_WAIT0();
            __syncthreads();
            uint32_t bb = sb + R_WB + (uint32_t)(ck & 1) * R_TB;
            // A = W smem [hi|lo] : segs hi(ck<4), lo(4<=ck<8), hi(ck>=8)
            int kwb = (ck < 8) ? ck * 256 : (ck - 8) * 256;
#pragma unroll
            for (int kk = 0; kk < 16; ++kk) {
                int kbw = kwb + kk * 16;
                int kbb = kk * 16;
                int r0 = 16 * mg + g;
                uint32_t o0 = sb + (uint32_t)(r0 * R_PW + kbw + 2 * c4) * 2;
                uint32_t o1 = o0 + 8 * R_PW * 2;
                uint32_t a0 = lds32(o0),      a1 = lds32(o1);
                uint32_t a2 = lds32(o0 + 16), a3 = lds32(o1 + 16);
#pragma unroll
                for (int s = 0; s < 2; ++s) {
                    int nr = 16 * ngp + 8 * s + g;
                    uint32_t ob = bb + (uint32_t)(nr * R_P + kbb + 2 * c4) * 2;
                    uint32_t b0 = lds32(ob), b1 = lds32(ob + 16);
                    mma16816(acc[s], a0, a1, a2, a3, b0, b1);
                }
            }
            __syncthreads();
        }
        // ---- stage D into SMEM ----
#pragma unroll
        for (int s = 0; s < 2; ++s) {
            int r = 16 * mg + g;
            int nb = 16 * ngp + 8 * s + 2 * c4;
            sts_f32(dbase + (uint32_t)(r * 65 + nb) * 4,           acc[s][0]);
            sts_f32(dbase + (uint32_t)(r * 65 + nb + 1) * 4,       acc[s][1]);
            sts_f32(dbase + (uint32_t)((r + 8) * 65 + nb) * 4,     acc[s][2]);
            sts_f32(dbase + (uint32_t)((r + 8) * 65 + nb + 1) * 4, acc[s][3]);
        }
        __syncthreads();
        // ---- cell update (2 cells per thread) ----
#pragma unroll
        for (int q = 0; q < 2; ++q) {
            int e = tid + q * 256;
            int u = e >> 6, b = e & 63;
            float4 xw = *(const float4*)(g_XW + (size_t)t * BG + (size_t)b * NG + m0 + 4 * u);
            float hf  = lds_f32(dbase + (uint32_t)((4 * u + 0) * 65 + b) * 4);
            float hi_ = lds_f32(dbase + (uint32_t)((4 * u + 1) * 65 + b) * 4);
            float hg  = lds_f32(dbase + (uint32_t)((4 * u + 2) * 65 + b) * 4);
            float ho  = lds_f32(dbase + (uint32_t)((4 * u + 3) * 65 + b) * 4);
            float f  = sigf(xw.x + hf);
            float i  = sigf(xw.y + hi_);
            float gg = tanhf(xw.z + hg);
            float o  = sigf(xw.w + ho);
            cc[q] = f * cc[q] + i * gg;
            float h = o * tanhf(cc[q]);
            out[(size_t)t * BH + (size_t)b * HH + j0 + u] = h;
            bf16 hh = __float2bfloat16(h);
            g_h2[wpar][b * KK2 + j0 + u]        = hh;
            g_h2[wpar][b * KK2 + 1024 + j0 + u] = __float2bfloat16(h - __bfloat162float(hh));
            if (t == TT - 1) {
                out[(size_t)TT * BH + (size_t)b * HH + j0 + u] = h;            // hx
                out[(size_t)TT * BH + BH + (size_t)b * HH + j0 + u] = cc[q];   // cx
            }
        }
        if (t < TT - 1) grid_barrier(t);
    }
}

// ---------------- launch ----------------
extern "C" void kernel_launch(void* const* d_in, const int* in_sizes, int n_in,
                              void* d_out, int out_size) {
    const float* inputs = (const float*)d_in[0];
    const float* Wf = (const float*)d_in[1];
    const float* bf_ = (const float*)d_in[2];
    const float* Wi = (const float*)d_in[3];
    const float* bi_ = (const float*)d_in[4];
    const float* Wg = (const float*)d_in[5];
    const float* bg_ = (const float*)d_in[6];
    const float* Wo = (const float*)d_in[7];
    const float* bo_ = (const float*)d_in[8];
    float* out = (float*)d_out;
    (void)in_sizes; (void)n_in; (void)out_size;

    cudaFuncSetAttribute(xproj_kernel, cudaFuncAttributeMaxDynamicSharedMemorySize, X_SMEM);
    cudaFuncSetAttribute(recur_kernel, cudaFuncAttributeMaxDynamicSharedMemorySize, R_SMEM);

    // 1) repack (K-MAJOR convention — correct bias) + zero barriers
    repack_kernel<<<(KK * NG) / 256, 256>>>(Wf, Wi, Wg, Wo, bf_, bi_, bg_, bo_);

    // 2) split inputs into [hi|lo]
    convx_kernel<<<(TT * BB * KK) / 256, 256>>>(inputs);

    // 3) x-projections: mma bf16 GEMM over virtual K''=3072 (round-9 core, fixed bias upstream)
    xproj_kernel<<<dim3(32, 256), 256, X_SMEM>>>();

    // 4) persistent recurrence: round-11 verbatim
    recur_kernel<<<128, 256, R_SMEM>>>(out);
}

// round 13
// speedup vs baseline: 4.1183x; 1.1792x over previous
#include <cuda_runtime.h>
#include <cuda_bf16.h>
#include <cstdint>
#include <cstddef>

// Problem dims
#define TT 512
#define BB 64
#define HH 1024
#define NG 4096              // 4*H, gate-interleaved: m (= n') = 4*j + gate(f,i,g,o)
#define KK 1024
#define KK2 2048             // stored K: [hi | lo]
#define BH (BB*HH)
#define BG (BB*NG)

typedef __nv_bfloat16 bf16;

// -------- device scratch (no allocations allowed) --------
__device__ __align__(16) bf16 g_Wx2[(size_t)NG * KK2]; // [m][hi|lo] for xproj
__device__ __align__(16) bf16 g_Wh2[(size_t)NG * KK2]; // [m][hi|lo] for recurrence
__device__ __align__(16) bf16 g_X2[(size_t)TT * BB * KK2]; // [s][hi|lo]
__device__ __align__(16) bf16 g_h2[2][BB * KK2];       // double-buffered h splits [b][hi|lo]
__device__ float g_ball[NG];
__device__ float g_XW[(size_t)TT * BB * NG];
__device__ unsigned int g_bar[TT];

// ---------------- low-level helpers (sm_80+ only) ----------------
__device__ __forceinline__ uint32_t smem_u32(const void* p) {
    uint32_t a;
    asm("{ .reg .u64 t; cvta.to.shared.u64 t, %1; cvt.u32.u64 %0, t; }" : "=r"(a) : "l"(p));
    return a;
}
__device__ __forceinline__ void cp16(uint32_t dst, const void* src) {
    asm volatile("cp.async.cg.shared.global [%0], [%1], 16;" :: "r"(dst), "l"(src) : "memory");
}
#define CP_COMMIT() asm volatile("cp.async.commit_group;" ::: "memory")
#define CP_WAIT1()  asm volatile("cp.async.wait_group 1;" ::: "memory")
#define CP_WAIT0()  asm volatile("cp.async.wait_group 0;" ::: "memory")

__device__ __forceinline__ uint32_t lds32(uint32_t a) {
    uint32_t v; asm volatile("ld.shared.b32 %0, [%1];" : "=r"(v) : "r"(a)); return v;
}
__device__ __forceinline__ float lds_f32(uint32_t a) {
    float v; asm volatile("ld.shared.f32 %0, [%1];" : "=f"(v) : "r"(a)); return v;
}
__device__ __forceinline__ void sts128(uint32_t a, uint4 v) {
    asm volatile("st.shared.v4.b32 [%0], {%1,%2,%3,%4};" :: "r"(a), "r"(v.x), "r"(v.y), "r"(v.z), "r"(v.w) : "memory");
}
__device__ __forceinline__ void sts_f32(uint32_t a, float v) {
    asm volatile("st.shared.f32 [%0], %1;" :: "r"(a), "f"(v) : "memory");
}
__device__ __forceinline__ void ldm4(uint32_t* r, uint32_t a) {
    asm volatile("ldmatrix.sync.aligned.m8n8.x4.shared.b16 {%0,%1,%2,%3}, [%4];"
        : "=r"(r[0]), "=r"(r[1]), "=r"(r[2]), "=r"(r[3]) : "r"(a));
}
__device__ __forceinline__ void mma16816(float* c,
                                         uint32_t a0, uint32_t a1, uint32_t a2, uint32_t a3,
                                         uint32_t b0, uint32_t b1) {
    asm volatile(
        "mma.sync.aligned.m16n8k16.row.col.f32.bf16.bf16.f32 "
        "{%0,%1,%2,%3}, {%4,%5,%6,%7}, {%8,%9}, {%0,%1,%2,%3};"
        : "+f"(c[0]), "+f"(c[1]), "+f"(c[2]), "+f"(c[3])
        : "r"(a0), "r"(a1), "r"(a2), "r"(a3), "r"(b0), "r"(b1));
}

// ---------------- prep kernels ----------------
// K-MAJOR index convention (idx = k*NG + n) — bias guard `idx < NG` valid only here.
__global__ void repack_kernel(const float* __restrict__ Wf, const float* __restrict__ Wi,
                              const float* __restrict__ Wg, const float* __restrict__ Wo,
                              const float* __restrict__ bf_, const float* __restrict__ bi_,
                              const float* __restrict__ bg_, const float* __restrict__ bo_) {
    int idx = blockIdx.x * 256 + threadIdx.x;   // idx = k*NG + n
    int k = idx >> 12;
    int n = idx & (NG - 1);
    int c = n >> 2, g = n & 3;
    const float* W = (g == 0) ? Wf : (g == 1) ? Wi : (g == 2) ? Wg : Wo;
    float wx = W[(size_t)k * HH + c];
    float wh = W[(size_t)(k + 1024) * HH + c];
    bf16 xh = __float2bfloat16(wx);
    g_Wx2[(size_t)n * KK2 + k]        = xh;
    g_Wx2[(size_t)n * KK2 + 1024 + k] = __float2bfloat16(wx - __bfloat162float(xh));
    bf16 hh = __float2bfloat16(wh);
    g_Wh2[(size_t)n * KK2 + k]        = hh;
    g_Wh2[(size_t)n * KK2 + 1024 + k] = __float2bfloat16(wh - __bfloat162float(hh));
    if (idx < NG) {
        const float* bv = (g == 0) ? bf_ : (g == 1) ? bi_ : (g == 2) ? bg_ : bo_;
        g_ball[idx] = bv[c];
    }
    if (idx < TT) g_bar[idx] = 0u;
}

__global__ void convx_kernel(const float* __restrict__ inp) {
    int idx = blockIdx.x * 256 + threadIdx.x;   // s*1024 + k
    int s = idx >> 10, k = idx & 1023;
    float v = inp[idx];
    bf16 h = __float2bfloat16(v);
    g_X2[(size_t)s * KK2 + k]        = h;
    g_X2[(size_t)s * KK2 + 1024 + k] = __float2bfloat16(v - __bfloat162float(h));
}

// ================= xproj (round-12 verbatim, verified): virtual K''=3072 bf16 GEMM =================
#define X_P   136                      // smem pitch (bf16)
#define X_TB  (128 * X_P * 2)          // 34816 B per tile buffer
#define X_SMEM (4 * X_TB)              // A0,A1,B0,B1 = 139264

__device__ __forceinline__ void xp_issue(uint32_t sb, int tid, int ck, int m0, int n0) {
    uint32_t ab = sb + (uint32_t)(ck & 1) * X_TB;
    uint32_t bb = sb + 2 * X_TB + (uint32_t)(ck & 1) * X_TB;
    int ka = (ck < 16) ? ck * 128 : (ck - 16) * 128;   // A: hi, lo, hi
    int kb = (ck < 8) ? ck * 128 : (ck - 8) * 128;     // B: hi, hi, lo
#pragma unroll
    for (int it = 0; it < 8; ++it) {
        int j = tid + it * 256;
        int r = j >> 4, kq = j & 15;
        uint32_t off = (uint32_t)(r * X_P + kq * 8) * 2;
        cp16(ab + off, g_Wx2 + (size_t)(m0 + r) * KK2 + ka + kq * 8);
        cp16(bb + off, g_X2 + (size_t)(n0 + r) * KK2 + kb + kq * 8);
    }
    CP_COMMIT();
}

__global__ __launch_bounds__(256) void xproj_kernel() {
    extern __shared__ __align__(16) char smem[];
    uint32_t sb = smem_u32(smem);
    const int tid = threadIdx.x;
    const int w = tid >> 5, lane = tid & 31;
    const int g = lane >> 2, c4 = lane & 3;
    const int m0 = blockIdx.x * 128, n0 = blockIdx.y * 128;
    const int mg = w >> 1, ngp = w & 1;

    float acc[2][8][4];
#pragma unroll
    for (int a = 0; a < 2; ++a)
#pragma unroll
        for (int b = 0; b < 8; ++b)
#pragma unroll
            for (int d = 0; d < 4; ++d) acc[a][b][d] = 0.f;

    xp_issue(sb, tid, 0, m0, n0);
    for (int ck = 0; ck < 24; ++ck) {
        if (ck < 23) { xp_issue(sb, tid, ck + 1, m0, n0); CP_WAIT1(); }
        else CP_WAIT0();
        __syncthreads();
        uint32_t ab = sb + (uint32_t)(ck & 1) * X_TB;
        uint32_t bb = sb + 2 * X_TB + (uint32_t)(ck & 1) * X_TB;
#pragma unroll
        for (int kk = 0; kk < 8; ++kk) {
            int kb = kk * 16;
            uint32_t a0[2], a1[2], a2[2], a3[2];
#pragma unroll
            for (int mt = 0; mt < 2; ++mt) {
                int r0 = 32 * mg + 16 * mt + g;
                uint32_t o0 = ab + (uint32_t)(r0 * X_P + kb + 2 * c4) * 2;
                uint32_t o1 = o0 + 8 * X_P * 2;
                a0[mt] = lds32(o0);      a1[mt] = lds32(o1);
                a2[mt] = lds32(o0 + 16); a3[mt] = lds32(o1 + 16);
            }
#pragma unroll
            for (int nt = 0; nt < 8; ++nt) {
                int nr = 64 * ngp + 8 * nt + g;
                uint32_t ob = bb + (uint32_t)(nr * X_P + kb + 2 * c4) * 2;
                uint32_t b0 = lds32(ob), b1 = lds32(ob + 16);
#pragma unroll
                for (int mt = 0; mt < 2; ++mt)
                    mma16816(acc[mt][nt], a0[mt], a1[mt], a2[mt], a3[mt], b0, b1);
            }
        }
        __syncthreads();
    }
#pragma unroll
    for (int mt = 0; mt < 2; ++mt) {
        int mrow = m0 + 32 * mg + 16 * mt + g;
        float bv0 = g_ball[mrow], bv1 = g_ball[mrow + 8];
#pragma unroll
        for (int nt = 0; nt < 8; ++nt) {
            int nrow = n0 + 64 * ngp + 8 * nt + 2 * c4;
            g_XW[(size_t)nrow * NG + mrow]           = acc[mt][nt][0] + bv0;
            g_XW[(size_t)(nrow + 1) * NG + mrow]     = acc[mt][nt][1] + bv0;
            g_XW[(size_t)nrow * NG + mrow + 8]       = acc[mt][nt][2] + bv1;
            g_XW[(size_t)(nrow + 1) * NG + mrow + 8] = acc[mt][nt][3] + bv1;
        }
    }
}

// ================= persistent recurrence: ldmatrix + physical-K chunks =================
// 128 CTAs x 256 threads. CTA: M32 (8 units) x N64 (all batches).
// W [hi|lo] resident in SMEM; h streamed as 8 physical chunks (k=128, hi+lo once).
// Per kk: ldmatrix.x4 (Ahi, Alo, Bhhi, Bhlo) + 6 mma (Ahi*Bhhi, Alo*Bhhi, Ahi*Bhlo).
#define R_PW  2056                     // W pitch (el): 4112B, 4112%128==16 -> ldmatrix conflict-free
#define R_WB  (32 * R_PW * 2)          // 131584
#define R_P   136                      // h chunk pitch (el): 272B, 272%128==16 -> conflict-free
#define R_SPL (64 * R_P * 2)           // 17408 per split (hhi or hlo)
#define R_TB  (2 * R_SPL)              // 34816 per chunk buffer
#define R_DOF (R_WB + 2 * R_TB)        // 201216
#define R_SMEM (R_DOF + 32 * 65 * 4)   // 209536

__device__ __forceinline__ void recur_issueB(uint32_t sb, int tid, int ck, int par) {
    uint32_t base = sb + R_WB + (uint32_t)(ck & 1) * R_TB;
#pragma unroll
    for (int it = 0; it < 4; ++it) {
        int j = tid + it * 256;            // 1024 16B-units per split
        int n = j >> 4, kq = j & 15;
        uint32_t d = base + (uint32_t)(n * R_P + kq * 8) * 2;
        const bf16* s = g_h2[par] + (size_t)n * KK2 + ck * 128 + kq * 8;
        cp16(d,         s);                // hhi chunk
        cp16(d + R_SPL, s + 1024);         // hlo chunk (same physical k, +1024 offset)
    }
    CP_COMMIT();
}

__device__ __forceinline__ float sigf(float x) { return 1.0f / (1.0f + __expf(-x)); }

__device__ __forceinline__ void grid_barrier(int t) {
    __syncthreads();
    if (threadIdx.x == 0) {
        __threadfence();
        atomicAdd(&g_bar[t], 1u);
        while (*((volatile unsigned int*)&g_bar[t]) < 128u) { __nanosleep(32); }
        __threadfence();
    }
    __syncthreads();
}

__global__ __launch_bounds__(256) void recur_kernel(float* __restrict__ out) {
    extern __shared__ __align__(16) char smem[];
    uint32_t sb = smem_u32(smem);
    const int tid = threadIdx.x;
    const int w = tid >> 5, lane = tid & 31;
    const int g = lane >> 2, c4 = lane & 3;
    const int m0 = blockIdx.x * 32;     // gate-row base
    const int j0 = blockIdx.x * 8;      // hidden-unit base
    const int mg = w & 1, ngp = w >> 1; // warp tile: m16 x n16

    // ldmatrix per-lane base offsets (row select + k/8 select)
    const int lrow = lane & 15;         // matrix row within 16-row group
    const int lko  = (lane >> 4) * 8;   // +8 k for upper half of lanes

    // ---- load this CTA's W [hi|lo] slice into SMEM once ----
#pragma unroll
    for (int it = 0; it < 32; ++it) {
        int j = tid + it * 256;             // 0..8191 16B-units
        int r = j >> 8, kq = j & 255;
        uint32_t off = (uint32_t)(r * R_PW + kq * 8) * 2;
        uint4 v = *(const uint4*)(g_Wh2 + (size_t)(m0 + r) * KK2 + kq * 8);
        sts128(sb + off, v);
    }
    __syncthreads();

    // ---- t = 0 (h_{-1} = 0): write h_0 splits into buffer 0 ----
    float cc[2];
#pragma unroll
    for (int q = 0; q < 2; ++q) {
        int e = tid + q * 256;
        int u = e >> 6, b = e & 63;
        float4 xw = *(const float4*)(g_XW + (size_t)b * NG + m0 + 4 * u);
        float i = sigf(xw.y), gg = tanhf(xw.z), o = sigf(xw.w);
        cc[q] = i * gg;
        float h = o * tanhf(cc[q]);
        out[(size_t)b * HH + j0 + u] = h;
        bf16 hh = __float2bfloat16(h);
        g_h2[0][b * KK2 + j0 + u]        = hh;
        g_h2[0][b * KK2 + 1024 + j0 + u] = __float2bfloat16(h - __bfloat162float(hh));
    }
    grid_barrier(0);

    const uint32_t dbase = sb + R_DOF;
    const uint32_t abase = sb + (uint32_t)((16 * mg + lrow) * R_PW) * 2;
    for (int t = 1; t < TT; ++t) {
        const int rpar = (t - 1) & 1;
        const int wpar = t & 1;
        float acc[2][4] = {{0.f, 0.f, 0.f, 0.f}, {0.f, 0.f, 0.f, 0.f}};
        recur_issueB(sb, tid, 0, rpar);
        for (int ck = 0; ck < 8; ++ck) {
            if (ck < 7) { recur_issueB(sb, tid, ck + 1, rpar); CP_WAIT1(); }
            else CP_WAIT0();
            __syncthreads();
            uint32_t bb = sb + R_WB + (uint32_t)(ck & 1) * R_TB
                        + (uint32_t)((16 * ngp + lrow) * R_P) * 2;
            const int kc = ck * 128;
#pragma unroll
            for (int kk = 0; kk < 8; ++kk) {
                uint32_t aoff = abase + (uint32_t)(kc + kk * 16 + lko) * 2;
                uint32_t boff = bb + (uint32_t)(kk * 16 + lko) * 2;
                uint32_t ah[4], al[4], bh[4], bl[4];
                ldm4(ah, aoff);                 // W hi fragment (m16 x k16)
                ldm4(al, aoff + 1024 * 2);      // W lo fragment
                ldm4(bh, boff);                 // h hi fragment (n16 x k16, both s)
                ldm4(bl, boff + R_SPL);         // h lo fragment
                // s=0: b0=m0, b1=m2 ; s=1: b0=m1, b1=m3
                mma16816(acc[0], ah[0], ah[1], ah[2], ah[3], bh[0], bh[2]);
                mma16816(acc[1], ah[0], ah[1], ah[2], ah[3], bh[1], bh[3]);
                mma16816(acc[0], al[0], al[1], al[2], al[3], bh[0], bh[2]);
                mma16816(acc[1], al[0], al[1], al[2], al[3], bh[1], bh[3]);
                mma16816(acc[0], ah[0], ah[1], ah[2], ah[3], bl[0], bl[2]);
                mma16816(acc[1], ah[0], ah[1], ah[2], ah[3], bl[1], bl[3]);
            }
            __syncthreads();
        }
        // ---- stage D into SMEM ----
#pragma unroll
        for (int s = 0; s < 2; ++s) {
            int r = 16 * mg + g;
            int nb = 16 * ngp + 8 * s + 2 * c4;
            sts_f32(dbase + (uint32_t)(r * 65 + nb) * 4,           acc[s][0]);
            sts_f32(dbase + (uint32_t)(r * 65 + nb + 1) * 4,       acc[s][1]);
            sts_f32(dbase + (uint32_t)((r + 8) * 65 + nb) * 4,     acc[s][2]);
            sts_f32(dbase + (uint32_t)((r + 8) * 65 + nb + 1) * 4, acc[s][3]);
        }
        __syncthreads();
        // ---- cell update (2 cells per thread) ----
#pragma unroll
        for (int q = 0; q < 2; ++q) {
            int e = tid + q * 256;
            int u = e >> 6, b = e & 63;
            float4 xw = *(const float4*)(g_XW + (size_t)t * BG + (size_t)b * NG + m0 + 4 * u);
            float hf  = lds_f32(dbase + (uint32_t)((4 * u + 0) * 65 + b) * 4);
            float hi_ = lds_f32(dbase + (uint32_t)((4 * u + 1) * 65 + b) * 4);
            float hg  = lds_f32(dbase + (uint32_t)((4 * u + 2) * 65 + b) * 4);
            float ho  = lds_f32(dbase + (uint32_t)((4 * u + 3) * 65 + b) * 4);
            float f  = sigf(xw.x + hf);
            float i  = sigf(xw.y + hi_);
            float gg = tanhf(xw.z + hg);
            float o  = sigf(xw.w + ho);
            cc[q] = f * cc[q] + i * gg;
            float h = o * tanhf(cc[q]);
            out[(size_t)t * BH + (size_t)b * HH + j0 + u] = h;
            bf16 hh = __float2bfloat16(h);
            g_h2[wpar][b * KK2 + j0 + u]        = hh;
            g_h2[wpar][b * KK2 + 1024 + j0 + u] = __float2bfloat16(h - __bfloat162float(hh));
            if (t == TT - 1) {
                out[(size_t)TT * BH + (size_t)b * HH + j0 + u] = h;            // hx
                out[(size_t)TT * BH + BH + (size_t)b * HH + j0 + u] = cc[q];   // cx
            }
        }
        if (t < TT - 1) grid_barrier(t);
    }
}

// ---------------- launch ----------------
extern "C" void kernel_launch(void* const* d_in, const int* in_sizes, int n_in,
                              void* d_out, int out_size) {
    const float* inputs = (const float*)d_in[0];
    const float* Wf = (const float*)d_in[1];
    const float* bf_ = (const float*)d_in[2];
    const float* Wi = (const float*)d_in[3];
    const float* bi_ = (const float*)d_in[4];
    const float* Wg = (const float*)d_in[5];
    const float* bg_ = (const float*)d_in[6];
    const float* Wo = (const float*)d_in[7];
    const float* bo_ = (const float*)d_in[8];
    float* out = (float*)d_out;
    (void)in_sizes; (void)n_in; (void)out_size;

    cudaFuncSetAttribute(xproj_kernel, cudaFuncAttributeMaxDynamicSharedMemorySize, X_SMEM);
    cudaFuncSetAttribute(recur_kernel, cudaFuncAttributeMaxDynamicSharedMemorySize, R_SMEM);

    // 1) repack (K-MAJOR convention — correct bias) + zero barriers
    repack_kernel<<<(KK * NG) / 256, 256>>>(Wf, Wi, Wg, Wo, bf_, bi_, bg_, bo_);

    // 2) split inputs into [hi|lo]
    convx_kernel<<<(TT * BB * KK) / 256, 256>>>(inputs);

    // 3) x-projections (round-12 verbatim, verified)
    xproj_kernel<<<dim3(32, 256), 256, X_SMEM>>>();

    // 4) persistent recurrence: ldmatrix + physical-K chunking
    recur_kernel<<<128, 256, R_SMEM>>>(out);
}

// round 14
// speedup vs baseline: 4.2948x; 1.0428x over previous
#include <cuda_runtime.h>
#include <cuda_bf16.h>
#include <cstdint>
#include <cstddef>

// Problem dims
#define TT 512
#define BB 64
#define HH 1024
#define NG 4096              // 4*H, gate-interleaved: m (= n') = 4*j + gate(f,i,g,o)
#define KK 1024
#define KK2 2048             // stored K: [hi | lo]
#define BH (BB*HH)
#define BG (BB*NG)

typedef __nv_bfloat16 bf16;

// -------- device scratch (no allocations allowed) --------
__device__ __align__(16) bf16 g_Wx2[(size_t)NG * KK2]; // [m][hi|lo] for xproj
__device__ __align__(16) bf16 g_Wh2[(size_t)NG * KK2]; // [m][hi|lo] for recurrence
__device__ __align__(16) bf16 g_X2[(size_t)TT * BB * KK2]; // [s][hi|lo]
__device__ __align__(16) bf16 g_h2[2][BB * KK2];       // double-buffered h splits [b][hi|lo]
__device__ float g_ball[NG];
__device__ float g_XW[(size_t)TT * BB * NG];
__device__ unsigned int g_bar[TT];

// ---------------- low-level helpers (sm_80+ only) ----------------
__device__ __forceinline__ uint32_t smem_u32(const void* p) {
    uint32_t a;
    asm("{ .reg .u64 t; cvta.to.shared.u64 t, %1; cvt.u32.u64 %0, t; }" : "=r"(a) : "l"(p));
    return a;
}
__device__ __forceinline__ void cp16(uint32_t dst, const void* src) {
    asm volatile("cp.async.cg.shared.global [%0], [%1], 16;" :: "r"(dst), "l"(src) : "memory");
}
#define CP_COMMIT() asm volatile("cp.async.commit_group;" ::: "memory")
#define CP_WAIT1()  asm volatile("cp.async.wait_group 1;" ::: "memory")
#define CP_WAIT0()  asm volatile("cp.async.wait_group 0;" ::: "memory")

__device__ __forceinline__ uint32_t lds32(uint32_t a) {
    uint32_t v; asm volatile("ld.shared.b32 %0, [%1];" : "=r"(v) : "r"(a)); return v;
}
__device__ __forceinline__ float lds_f32(uint32_t a) {
    float v; asm volatile("ld.shared.f32 %0, [%1];" : "=f"(v) : "r"(a)); return v;
}
__device__ __forceinline__ void sts128(uint32_t a, uint4 v) {
    asm volatile("st.shared.v4.b32 [%0], {%1,%2,%3,%4};" :: "r"(a), "r"(v.x), "r"(v.y), "r"(v.z), "r"(v.w) : "memory");
}
__device__ __forceinline__ void sts_f32(uint32_t a, float v) {
    asm volatile("st.shared.f32 [%0], %1;" :: "r"(a), "f"(v) : "memory");
}
__device__ __forceinline__ void ldm4(uint32_t* r, uint32_t a) {
    asm volatile("ldmatrix.sync.aligned.m8n8.x4.shared.b16 {%0,%1,%2,%3}, [%4];"
        : "=r"(r[0]), "=r"(r[1]), "=r"(r[2]), "=r"(r[3]) : "r"(a));
}
__device__ __forceinline__ void mma16816(float* c,
                                         uint32_t a0, uint32_t a1, uint32_t a2, uint32_t a3,
                                         uint32_t b0, uint32_t b1) {
    asm volatile(
        "mma.sync.aligned.m16n8k16.row.col.f32.bf16.bf16.f32 "
        "{%0,%1,%2,%3}, {%4,%5,%6,%7}, {%8,%9}, {%0,%1,%2,%3};"
        : "+f"(c[0]), "+f"(c[1]), "+f"(c[2]), "+f"(c[3])
        : "r"(a0), "r"(a1), "r"(a2), "r"(a3), "r"(b0), "r"(b1));
}

// ---------------- prep kernels ----------------
// K-MAJOR index convention (idx = k*NG + n) — bias guard `idx < NG` valid only here.
__global__ void repack_kernel(const float* __restrict__ Wf, const float* __restrict__ Wi,
                              const float* __restrict__ Wg, const float* __restrict__ Wo,
                              const float* __restrict__ bf_, const float* __restrict__ bi_,
                              const float* __restrict__ bg_, const float* __restrict__ bo_) {
    int idx = blockIdx.x * 256 + threadIdx.x;   // idx = k*NG + n
    int k = idx >> 12;
    int n = idx & (NG - 1);
    int c = n >> 2, g = n & 3;
    const float* W = (g == 0) ? Wf : (g == 1) ? Wi : (g == 2) ? Wg : Wo;
    float wx = W[(size_t)k * HH + c];
    float wh = W[(size_t)(k + 1024) * HH + c];
    bf16 xh = __float2bfloat16(wx);
    g_Wx2[(size_t)n * KK2 + k]        = xh;
    g_Wx2[(size_t)n * KK2 + 1024 + k] = __float2bfloat16(wx - __bfloat162float(xh));
    bf16 hh = __float2bfloat16(wh);
    g_Wh2[(size_t)n * KK2 + k]        = hh;
    g_Wh2[(size_t)n * KK2 + 1024 + k] = __float2bfloat16(wh - __bfloat162float(hh));
    if (idx < NG) {
        const float* bv = (g == 0) ? bf_ : (g == 1) ? bi_ : (g == 2) ? bg_ : bo_;
        g_ball[idx] = bv[c];
    }
    if (idx < TT) g_bar[idx] = 0u;
}

__global__ void convx_kernel(const float* __restrict__ inp) {
    int idx = blockIdx.x * 256 + threadIdx.x;   // s*1024 + k
    int s = idx >> 10, k = idx & 1023;
    float v = inp[idx];
    bf16 h = __float2bfloat16(v);
    g_X2[(size_t)s * KK2 + k]        = h;
    g_X2[(size_t)s * KK2 + 1024 + k] = __float2bfloat16(v - __bfloat162float(h));
}

// ================= xproj (round-12 verbatim, verified): virtual K''=3072 bf16 GEMM =================
#define X_P   136                      // smem pitch (bf16)
#define X_TB  (128 * X_P * 2)          // 34816 B per tile buffer
#define X_SMEM (4 * X_TB)              // A0,A1,B0,B1 = 139264

__device__ __forceinline__ void xp_issue(uint32_t sb, int tid, int ck, int m0, int n0) {
    uint32_t ab = sb + (uint32_t)(ck & 1) * X_TB;
    uint32_t bb = sb + 2 * X_TB + (uint32_t)(ck & 1) * X_TB;
    int ka = (ck < 16) ? ck * 128 : (ck - 16) * 128;   // A: hi, lo, hi
    int kb = (ck < 8) ? ck * 128 : (ck - 8) * 128;     // B: hi, hi, lo
#pragma unroll
    for (int it = 0; it < 8; ++it) {
        int j = tid + it * 256;
        int r = j >> 4, kq = j & 15;
        uint32_t off = (uint32_t)(r * X_P + kq * 8) * 2;
        cp16(ab + off, g_Wx2 + (size_t)(m0 + r) * KK2 + ka + kq * 8);
        cp16(bb + off, g_X2 + (size_t)(n0 + r) * KK2 + kb + kq * 8);
    }
    CP_COMMIT();
}

__global__ __launch_bounds__(256) void xproj_kernel() {
    extern __shared__ __align__(16) char smem[];
    uint32_t sb = smem_u32(smem);
    const int tid = threadIdx.x;
    const int w = tid >> 5, lane = tid & 31;
    const int g = lane >> 2, c4 = lane & 3;
    const int m0 = blockIdx.x * 128, n0 = blockIdx.y * 128;
    const int mg = w >> 1, ngp = w & 1;

    float acc[2][8][4];
#pragma unroll
    for (int a = 0; a < 2; ++a)
#pragma unroll
        for (int b = 0; b < 8; ++b)
#pragma unroll
            for (int d = 0; d < 4; ++d) acc[a][b][d] = 0.f;

    xp_issue(sb, tid, 0, m0, n0);
    for (int ck = 0; ck < 24; ++ck) {
        if (ck < 23) { xp_issue(sb, tid, ck + 1, m0, n0); CP_WAIT1(); }
        else CP_WAIT0();
        __syncthreads();
        uint32_t ab = sb + (uint32_t)(ck & 1) * X_TB;
        uint32_t bb = sb + 2 * X_TB + (uint32_t)(ck & 1) * X_TB;
#pragma unroll
        for (int kk = 0; kk < 8; ++kk) {
            int kb = kk * 16;
            uint32_t a0[2], a1[2], a2[2], a3[2];
#pragma unroll
            for (int mt = 0; mt < 2; ++mt) {
                int r0 = 32 * mg + 16 * mt + g;
                uint32_t o0 = ab + (uint32_t)(r0 * X_P + kb + 2 * c4) * 2;
                uint32_t o1 = o0 + 8 * X_P * 2;
                a0[mt] = lds32(o0);      a1[mt] = lds32(o1);
                a2[mt] = lds32(o0 + 16); a3[mt] = lds32(o1 + 16);
            }
#pragma unroll
            for (int nt = 0; nt < 8; ++nt) {
                int nr = 64 * ngp + 8 * nt + g;
                uint32_t ob = bb + (uint32_t)(nr * X_P + kb + 2 * c4) * 2;
                uint32_t b0 = lds32(ob), b1 = lds32(ob + 16);
#pragma unroll
                for (int mt = 0; mt < 2; ++mt)
                    mma16816(acc[mt][nt], a0[mt], a1[mt], a2[mt], a3[mt], b0, b1);
            }
        }
        __syncthreads();
    }
#pragma unroll
    for (int mt = 0; mt < 2; ++mt) {
        int mrow = m0 + 32 * mg + 16 * mt + g;
        float bv0 = g_ball[mrow], bv1 = g_ball[mrow + 8];
#pragma unroll
        for (int nt = 0; nt < 8; ++nt) {
            int nrow = n0 + 64 * ngp + 8 * nt + 2 * c4;
            g_XW[(size_t)nrow * NG + mrow]           = acc[mt][nt][0] + bv0;
            g_XW[(size_t)(nrow + 1) * NG + mrow]     = acc[mt][nt][1] + bv0;
            g_XW[(size_t)nrow * NG + mrow + 8]       = acc[mt][nt][2] + bv1;
            g_XW[(size_t)(nrow + 1) * NG + mrow + 8] = acc[mt][nt][3] + bv1;
        }
    }
}

// ================= persistent recurrence: 512 threads, 2-way k-split =================
// 128 CTAs x 512 threads. CTA: M32 (8 units) x N64 (all batches).
// Warp grid: mg(2) x ngp(4) x kg(2). kg halves split kk 0..3 / 4..7 of each chunk
// into private fp32 partials (D0, D1 in smem), summed in the cell update.
#define R_PW  2056                     // W pitch (el): 4112B % 128 == 16 -> ldmatrix conflict-free
#define R_WB  (32 * R_PW * 2)          // 131584
#define R_P   136                      // h chunk pitch (el): 272B % 128 == 16 -> conflict-free
#define R_SPL (64 * R_P * 2)           // 17408 per split (hhi or hlo)
#define R_TB  (2 * R_SPL)              // 34816 per chunk buffer
#define R_DOF (R_WB + 2 * R_TB)        // 201216
#define R_DSZ (32 * 65 * 4)            // 8320 per D partial
#define R_SMEM (R_DOF + 2 * R_DSZ)     // 217856

__device__ __forceinline__ void recur_issueB(uint32_t sb, int tid, int ck, int par) {
    uint32_t base = sb + R_WB + (uint32_t)(ck & 1) * R_TB;
#pragma unroll
    for (int it = 0; it < 2; ++it) {
        int j = tid + it * 512;            // 1024 16B-units per split
        int n = j >> 4, kq = j & 15;
        uint32_t d = base + (uint32_t)(n * R_P + kq * 8) * 2;
        const bf16* s = g_h2[par] + (size_t)n * KK2 + ck * 128 + kq * 8;
        cp16(d,         s);                // hhi chunk
        cp16(d + R_SPL, s + 1024);         // hlo chunk
    }
    CP_COMMIT();
}

__device__ __forceinline__ float sigf(float x) { return 1.0f / (1.0f + __expf(-x)); }

__device__ __forceinline__ void grid_barrier(int t) {
    __syncthreads();
    if (threadIdx.x == 0) {
        __threadfence();
        atomicAdd(&g_bar[t], 1u);
        while (*((volatile unsigned int*)&g_bar[t]) < 128u) { __nanosleep(32); }
        __threadfence();
    }
    __syncthreads();
}

__global__ __launch_bounds__(512) void recur_kernel(float* __restrict__ out) {
    extern __shared__ __align__(16) char smem[];
    uint32_t sb = smem_u32(smem);
    const int tid = threadIdx.x;
    const int w = tid >> 5, lane = tid & 31;
    const int g = lane >> 2, c4 = lane & 3;
    const int m0 = blockIdx.x * 32;     // gate-row base
    const int j0 = blockIdx.x * 8;      // hidden-unit base
    const int mg = w & 1;               // m16 tile
    const int ngp = (w >> 1) & 3;       // n16 tile (4 of them = N64)
    const int kg = w >> 3;              // k-split half

    // ldmatrix per-lane base offsets
    const int lrow = lane & 15;
    const int lko  = (lane >> 4) * 8;

    // ---- load this CTA's W [hi|lo] slice into SMEM once ----
#pragma unroll
    for (int it = 0; it < 16; ++it) {
        int j = tid + it * 512;             // 0..8191 16B-units
        int r = j >> 8, kq = j & 255;
        uint32_t off = (uint32_t)(r * R_PW + kq * 8) * 2;
        uint4 v = *(const uint4*)(g_Wh2 + (size_t)(m0 + r) * KK2 + kq * 8);
        sts128(sb + off, v);
    }
    __syncthreads();

    // ---- t = 0 (h_{-1} = 0): 1 cell per thread ----
    float cc;
    {
        int u = tid >> 6, b = tid & 63;
        float4 xw = *(const float4*)(g_XW + (size_t)b * NG + m0 + 4 * u);
        float i = sigf(xw.y), gg = tanhf(xw.z), o = sigf(xw.w);
        cc = i * gg;
        float h = o * tanhf(cc);
        out[(size_t)b * HH + j0 + u] = h;
        bf16 hh = __float2bfloat16(h);
        g_h2[0][b * KK2 + j0 + u]        = hh;
        g_h2[0][b * KK2 + 1024 + j0 + u] = __float2bfloat16(h - __bfloat162float(hh));
    }
    grid_barrier(0);

    const uint32_t d0 = sb + R_DOF;
    const uint32_t dk = d0 + (uint32_t)kg * R_DSZ;   // this warp's D partial
    const uint32_t abase = sb + (uint32_t)((16 * mg + lrow) * R_PW) * 2;
    const int kk0 = kg * 4;
    for (int t = 1; t < TT; ++t) {
        const int rpar = (t - 1) & 1;
        const int wpar = t & 1;
        float acc[2][4] = {{0.f, 0.f, 0.f, 0.f}, {0.f, 0.f, 0.f, 0.f}};
        recur_issueB(sb, tid, 0, rpar);
        for (int ck = 0; ck < 8; ++ck) {
            if (ck < 7) { recur_issueB(sb, tid, ck + 1, rpar); CP_WAIT1(); }
            else CP_WAIT0();
            __syncthreads();
            uint32_t bb = sb + R_WB + (uint32_t)(ck & 1) * R_TB
                        + (uint32_t)((16 * ngp + lrow) * R_P) * 2;
            const int kc = ck * 128;
#pragma unroll
            for (int kk = 0; kk < 4; ++kk) {
                uint32_t aoff = abase + (uint32_t)(kc + (kk0 + kk) * 16 + lko) * 2;
                uint32_t boff = bb + (uint32_t)((kk0 + kk) * 16 + lko) * 2;
                uint32_t ah[4], al[4], bh[4], bl[4];
                ldm4(ah, aoff);                 // W hi fragment (m16 x k16)
                ldm4(al, aoff + 1024 * 2);      // W lo fragment
                ldm4(bh, boff);                 // h hi fragment (n16 x k16)
                ldm4(bl, boff + R_SPL);         // h lo fragment
                mma16816(acc[0], ah[0], ah[1], ah[2], ah[3], bh[0], bh[2]);
                mma16816(acc[1], ah[0], ah[1], ah[2], ah[3], bh[1], bh[3]);
                mma16816(acc[0], al[0], al[1], al[2], al[3], bh[0], bh[2]);
                mma16816(acc[1], al[0], al[1], al[2], al[3], bh[1], bh[3]);
                mma16816(acc[0], ah[0], ah[1], ah[2], ah[3], bl[0], bl[2]);
                mma16816(acc[1], ah[0], ah[1], ah[2], ah[3], bl[1], bl[3]);
            }
            __syncthreads();
        }
        // ---- stage D partial into this kg's smem buffer ----
#pragma unroll
        for (int s = 0; s < 2; ++s) {
            int r = 16 * mg + g;
            int nb = 16 * ngp + 8 * s + 2 * c4;
            sts_f32(dk + (uint32_t)(r * 65 + nb) * 4,           acc[s][0]);
            sts_f32(dk + (uint32_t)(r * 65 + nb + 1) * 4,       acc[s][1]);
            sts_f32(dk + (uint32_t)((r + 8) * 65 + nb) * 4,     acc[s][2]);
            sts_f32(dk + (uint32_t)((r + 8) * 65 + nb + 1) * 4, acc[s][3]);
        }
        __syncthreads();
        // ---- cell update: 1 cell per thread, sum the two k-split partials ----
        {
            int u = tid >> 6, b = tid & 63;
            float4 xw = *(const float4*)(g_XW + (size_t)t * BG + (size_t)b * NG + m0 + 4 * u);
            float hf  = lds_f32(d0 + (uint32_t)((4 * u + 0) * 65 + b) * 4)
                      + lds_f32(d0 + R_DSZ + (uint32_t)((4 * u + 0) * 65 + b) * 4);
            float hi_ = lds_f32(d0 + (uint32_t)((4 * u + 1) * 65 + b) * 4)
                      + lds_f32(d0 + R_DSZ + (uint32_t)((4 * u + 1) * 65 + b) * 4);
            float hg  = lds_f32(d0 + (uint32_t)((4 * u + 2) * 65 + b) * 4)
                      + lds_f32(d0 + R_DSZ + (uint32_t)((4 * u + 2) * 65 + b) * 4);
            float ho  = lds_f32(d0 + (uint32_t)((4 * u + 3) * 65 + b) * 4)
                      + lds_f32(d0 + R_DSZ + (uint32_t)((4 * u + 3) * 65 + b) * 4);
            float f  = sigf(xw.x + hf);
            float i  = sigf(xw.y + hi_);
            float gg = tanhf(xw.z + hg);
            float o  = sigf(xw.w + ho);
            cc = f * cc + i * gg;
            float h = o * tanhf(cc);
            out[(size_t)t * BH + (size_t)b * HH + j0 + u] = h;
            bf16 hh = __float2bfloat16(h);
            g_h2[wpar][b * KK2 + j0 + u]        = hh;
            g_h2[wpar][b * KK2 + 1024 + j0 + u] = __float2bfloat16(h - __bfloat162float(hh));
            if (t == TT - 1) {
                out[(size_t)TT * BH + (size_t)b * HH + j0 + u] = h;            // hx
                out[(size_t)TT * BH + BH + (size_t)b * HH + j0 + u] = cc;      // cx
            }
        }
        if (t < TT - 1) grid_barrier(t);
    }
}

// ---------------- launch ----------------
extern "C" void kernel_launch(void* const* d_in, const int* in_sizes, int n_in,
                              void* d_out, int out_size) {
    const float* inputs = (const float*)d_in[0];
    const float* Wf = (const float*)d_in[1];
    const float* bf_ = (const float*)d_in[2];
    const float* Wi = (const float*)d_in[3];
    const float* bi_ = (const float*)d_in[4];
    const float* Wg = (const float*)d_in[5];
    const float* bg_ = (const float*)d_in[6];
    const float* Wo = (const float*)d_in[7];
    const float* bo_ = (const float*)d_in[8];
    float* out = (float*)d_out;
    (void)in_sizes; (void)n_in; (void)out_size;

    cudaFuncSetAttribute(xproj_kernel, cudaFuncAttributeMaxDynamicSharedMemorySize, X_SMEM);
    cudaFuncSetAttribute(recur_kernel, cudaFuncAttributeMaxDynamicSharedMemorySize, R_SMEM);

    // 1) repack (K-MAJOR convention — correct bias) + zero barriers
    repack_kernel<<<(KK * NG) / 256, 256>>>(Wf, Wi, Wg, Wo, bf_, bi_, bg_, bo_);

    // 2) split inputs into [hi|lo]
    convx_kernel<<<(TT * BB * KK) / 256, 256>>>(inputs);

    // 3) x-projections (round-12 verbatim, verified)
    xproj_kernel<<<dim3(32, 256), 256, X_SMEM>>>();

    // 4) persistent recurrence: 512 threads, 2-way k-split
    recur_kernel<<<128, 512, R_SMEM>>>(out);
}

// round 15
// speedup vs baseline: 4.3287x; 1.0079x over previous
#include <cuda_runtime.h>
#include <cuda_bf16.h>
#include <cstdint>
#include <cstddef>

// Problem dims
#define TT 512
#define BB 64
#define HH 1024
#define NG 4096              // 4*H, gate-interleaved: m (= n') = 4*j + gate(f,i,g,o)
#define KK 1024
#define KK2 2048             // stored K: [hi | lo]
#define BH (BB*HH)
#define BG (BB*NG)

typedef __nv_bfloat16 bf16;

// -------- device scratch (no allocations allowed) --------
__device__ __align__(16) bf16 g_Wx2[(size_t)NG * KK2]; // [m][hi|lo] for xproj
__device__ __align__(16) bf16 g_Wh2[(size_t)NG * KK2]; // [m][hi|lo] for recurrence
__device__ __align__(16) bf16 g_X2[(size_t)TT * BB * KK2]; // [s][hi|lo]
__device__ __align__(16) bf16 g_h2[2][BB * KK2];       // double-buffered h splits [b][hi|lo]
__device__ float g_ball[NG];
__device__ float g_XW[(size_t)TT * BB * NG];
__device__ unsigned int g_bar[TT];

// ---------------- low-level helpers (sm_80+ only) ----------------
__device__ __forceinline__ uint32_t smem_u32(const void* p) {
    uint32_t a;
    asm("{ .reg .u64 t; cvta.to.shared.u64 t, %1; cvt.u32.u64 %0, t; }" : "=r"(a) : "l"(p));
    return a;
}
__device__ __forceinline__ void cp16(uint32_t dst, const void* src) {
    asm volatile("cp.async.cg.shared.global [%0], [%1], 16;" :: "r"(dst), "l"(src) : "memory");
}
#define CP_COMMIT() asm volatile("cp.async.commit_group;" ::: "memory")
#define CP_WAIT1()  asm volatile("cp.async.wait_group 1;" ::: "memory")
#define CP_WAIT0()  asm volatile("cp.async.wait_group 0;" ::: "memory")

__device__ __forceinline__ float lds_f32(uint32_t a) {
    float v; asm volatile("ld.shared.f32 %0, [%1];" : "=f"(v) : "r"(a)); return v;
}
__device__ __forceinline__ void sts128(uint32_t a, uint4 v) {
    asm volatile("st.shared.v4.b32 [%0], {%1,%2,%3,%4};" :: "r"(a), "r"(v.x), "r"(v.y), "r"(v.z), "r"(v.w) : "memory");
}
__device__ __forceinline__ void sts_f32(uint32_t a, float v) {
    asm volatile("st.shared.f32 [%0], %1;" :: "r"(a), "f"(v) : "memory");
}
__device__ __forceinline__ void ldm4(uint32_t* r, uint32_t a) {
    asm volatile("ldmatrix.sync.aligned.m8n8.x4.shared.b16 {%0,%1,%2,%3}, [%4];"
        : "=r"(r[0]), "=r"(r[1]), "=r"(r[2]), "=r"(r[3]) : "r"(a));
}
__device__ __forceinline__ void mma16816(float* c,
                                         uint32_t a0, uint32_t a1, uint32_t a2, uint32_t a3,
                                         uint32_t b0, uint32_t b1) {
    asm volatile(
        "mma.sync.aligned.m16n8k16.row.col.f32.bf16.bf16.f32 "
        "{%0,%1,%2,%3}, {%4,%5,%6,%7}, {%8,%9}, {%0,%1,%2,%3};"
        : "+f"(c[0]), "+f"(c[1]), "+f"(c[2]), "+f"(c[3])
        : "r"(a0), "r"(a1), "r"(a2), "r"(a3), "r"(b0), "r"(b1));
}

// ---------------- prep kernels ----------------
// K-MAJOR index convention (idx = k*NG + n) — bias guard `idx < NG` valid only here.
__global__ void repack_kernel(const float* __restrict__ Wf, const float* __restrict__ Wi,
                              const float* __restrict__ Wg, const float* __restrict__ Wo,
                              const float* __restrict__ bf_, const float* __restrict__ bi_,
                              const float* __restrict__ bg_, const float* __restrict__ bo_) {
    int idx = blockIdx.x * 256 + threadIdx.x;   // idx = k*NG + n
    int k = idx >> 12;
    int n = idx & (NG - 1);
    int c = n >> 2, g = n & 3;
    const float* W = (g == 0) ? Wf : (g == 1) ? Wi : (g == 2) ? Wg : Wo;
    float wx = W[(size_t)k * HH + c];
    float wh = W[(size_t)(k + 1024) * HH + c];
    bf16 xh = __float2bfloat16(wx);
    g_Wx2[(size_t)n * KK2 + k]        = xh;
    g_Wx2[(size_t)n * KK2 + 1024 + k] = __float2bfloat16(wx - __bfloat162float(xh));
    bf16 hh = __float2bfloat16(wh);
    g_Wh2[(size_t)n * KK2 + k]        = hh;
    g_Wh2[(size_t)n * KK2 + 1024 + k] = __float2bfloat16(wh - __bfloat162float(hh));
    if (idx < NG) {
        const float* bv = (g == 0) ? bf_ : (g == 1) ? bi_ : (g == 2) ? bg_ : bo_;
        g_ball[idx] = bv[c];
    }
    if (idx < TT) g_bar[idx] = 0u;
}

__global__ void convx_kernel(const float* __restrict__ inp) {
    int idx = blockIdx.x * 256 + threadIdx.x;   // s*1024 + k
    int s = idx >> 10, k = idx & 1023;
    float v = inp[idx];
    bf16 h = __float2bfloat16(v);
    g_X2[(size_t)s * KK2 + k]        = h;
    g_X2[(size_t)s * KK2 + 1024 + k] = __float2bfloat16(v - __bfloat162float(h));
}

// ================= xproj: virtual K''=3072 bf16 GEMM, ldmatrix fragments =================
// CTA tile M128 x N128, chunk 128 k'', 24 chunks, double-buffered cp.async.
// X_P=136 el -> 272B/row, 272%128==16: 8 consecutive rows hit distinct 16B banks (ldmatrix-safe,
// same property as the verified recurrence pitch).
#define X_P   136                      // smem pitch (bf16)
#define X_TB  (128 * X_P * 2)          // 34816 B per tile buffer
#define X_SMEM (4 * X_TB)              // A0,A1,B0,B1 = 139264

__device__ __forceinline__ void xp_issue(uint32_t sb, int tid, int ck, int m0, int n0) {
    uint32_t ab = sb + (uint32_t)(ck & 1) * X_TB;
    uint32_t bb = sb + 2 * X_TB + (uint32_t)(ck & 1) * X_TB;
    int ka = (ck < 16) ? ck * 128 : (ck - 16) * 128;   // A: hi, lo, hi
    int kb = (ck < 8) ? ck * 128 : (ck - 8) * 128;     // B: hi, hi, lo
#pragma unroll
    for (int it = 0; it < 8; ++it) {
        int j = tid + it * 256;
        int r = j >> 4, kq = j & 15;
        uint32_t off = (uint32_t)(r * X_P + kq * 8) * 2;
        cp16(ab + off, g_Wx2 + (size_t)(m0 + r) * KK2 + ka + kq * 8);
        cp16(bb + off, g_X2 + (size_t)(n0 + r) * KK2 + kb + kq * 8);
    }
    CP_COMMIT();
}

__global__ __launch_bounds__(256) void xproj_kernel() {
    extern __shared__ __align__(16) char smem[];
    uint32_t sb = smem_u32(smem);
    const int tid = threadIdx.x;
    const int w = tid >> 5, lane = tid & 31;
    const int g = lane >> 2, c4 = lane & 3;
    const int m0 = blockIdx.x * 128, n0 = blockIdx.y * 128;
    const int mg = w >> 1, ngp = w & 1;     // warp tile: m32 x n64
    const int lrow = lane & 15;             // ldmatrix row select
    const int lko  = (lane >> 4) * 8;       // ldmatrix k-half select

    float acc[2][8][4];
#pragma unroll
    for (int a = 0; a < 2; ++a)
#pragma unroll
        for (int b = 0; b < 8; ++b)
#pragma unroll
            for (int d = 0; d < 4; ++d) acc[a][b][d] = 0.f;

    xp_issue(sb, tid, 0, m0, n0);
    for (int ck = 0; ck < 24; ++ck) {
        if (ck < 23) { xp_issue(sb, tid, ck + 1, m0, n0); CP_WAIT1(); }
        else CP_WAIT0();
        __syncthreads();
        uint32_t ab = sb + (uint32_t)(ck & 1) * X_TB;
        uint32_t bb = sb + 2 * X_TB + (uint32_t)(ck & 1) * X_TB;
#pragma unroll
        for (int kk = 0; kk < 8; ++kk) {
            int kb = kk * 16 + lko;
            uint32_t af[2][4], bf_[4][4];
#pragma unroll
            for (int mt = 0; mt < 2; ++mt)
                ldm4(af[mt], ab + (uint32_t)((32 * mg + 16 * mt + lrow) * X_P + kb) * 2);
#pragma unroll
            for (int nt2 = 0; nt2 < 4; ++nt2)
                ldm4(bf_[nt2], bb + (uint32_t)((64 * ngp + 16 * nt2 + lrow) * X_P + kb) * 2);
#pragma unroll
            for (int nt2 = 0; nt2 < 4; ++nt2) {
#pragma unroll
                for (int hf2 = 0; hf2 < 2; ++hf2) {
                    uint32_t b0 = bf_[nt2][hf2], b1 = bf_[nt2][hf2 + 2];
#pragma unroll
                    for (int mt = 0; mt < 2; ++mt)
                        mma16816(acc[mt][2 * nt2 + hf2],
                                 af[mt][0], af[mt][1], af[mt][2], af[mt][3], b0, b1);
                }
            }
        }
        __syncthreads();
    }
#pragma unroll
    for (int mt = 0; mt < 2; ++mt) {
        int mrow = m0 + 32 * mg + 16 * mt + g;
        float bv0 = g_ball[mrow], bv1 = g_ball[mrow + 8];
#pragma unroll
        for (int nt = 0; nt < 8; ++nt) {
            int nrow = n0 + 64 * ngp + 8 * nt + 2 * c4;
            g_XW[(size_t)nrow * NG + mrow]           = acc[mt][nt][0] + bv0;
            g_XW[(size_t)(nrow + 1) * NG + mrow]     = acc[mt][nt][1] + bv0;
            g_XW[(size_t)nrow * NG + mrow + 8]       = acc[mt][nt][2] + bv1;
            g_XW[(size_t)(nrow + 1) * NG + mrow + 8] = acc[mt][nt][3] + bv1;
        }
    }
}

// ================= persistent recurrence: 512 threads, 2-way k-split (round-14 + xw prefetch) =================
#define R_PW  2056                     // W pitch (el): 4112B % 128 == 16 -> ldmatrix conflict-free
#define R_WB  (32 * R_PW * 2)          // 131584
#define R_P   136                      // h chunk pitch (el)
#define R_SPL (64 * R_P * 2)           // 17408 per split (hhi or hlo)
#define R_TB  (2 * R_SPL)              // 34816 per chunk buffer
#define R_DOF (R_WB + 2 * R_TB)        // 201216
#define R_DSZ (32 * 65 * 4)            // 8320 per D partial
#define R_SMEM (R_DOF + 2 * R_DSZ)     // 217856

__device__ __forceinline__ void recur_issueB(uint32_t sb, int tid, int ck, int par) {
    uint32_t base = sb + R_WB + (uint32_t)(ck & 1) * R_TB;
#pragma unroll
    for (int it = 0; it < 2; ++it) {
        int j = tid + it * 512;            // 1024 16B-units per split
        int n = j >> 4, kq = j & 15;
        uint32_t d = base + (uint32_t)(n * R_P + kq * 8) * 2;
        const bf16* s = g_h2[par] + (size_t)n * KK2 + ck * 128 + kq * 8;
        cp16(d,         s);                // hhi chunk
        cp16(d + R_SPL, s + 1024);         // hlo chunk
    }
    CP_COMMIT();
}

__device__ __forceinline__ float sigf(float x) { return 1.0f / (1.0f + __expf(-x)); }

__device__ __forceinline__ void grid_barrier(int t) {
    __syncthreads();
    if (threadIdx.x == 0) {
        __threadfence();
        atomicAdd(&g_bar[t], 1u);
        while (*((volatile unsigned int*)&g_bar[t]) < 128u) { __nanosleep(32); }
        __threadfence();
    }
    __syncthreads();
}

__global__ __launch_bounds__(512) void recur_kernel(float* __restrict__ out) {
    extern __shared__ __align__(16) char smem[];
    uint32_t sb = smem_u32(smem);
    const int tid = threadIdx.x;
    const int w = tid >> 5, lane = tid & 31;
    const int g = lane >> 2, c4 = lane & 3;
    const int m0 = blockIdx.x * 32;     // gate-row base
    const int j0 = blockIdx.x * 8;      // hidden-unit base
    const int mg = w & 1;               // m16 tile
    const int ngp = (w >> 1) & 3;       // n16 tile
    const int kg = w >> 3;              // k-split half
    const int lrow = lane & 15;
    const int lko  = (lane >> 4) * 8;

    // ---- load this CTA's W [hi|lo] slice into SMEM once ----
#pragma unroll
    for (int it = 0; it < 16; ++it) {
        int j = tid + it * 512;
        int r = j >> 8, kq = j & 255;
        uint32_t off = (uint32_t)(r * R_PW + kq * 8) * 2;
        uint4 v = *(const uint4*)(g_Wh2 + (size_t)(m0 + r) * KK2 + kq * 8);
        sts128(sb + off, v);
    }
    __syncthreads();

    // ---- t = 0 (h_{-1} = 0): 1 cell per thread ----
    float cc;
    const int cu = tid >> 6, cb = tid & 63;   // this thread's cell (unit, batch)
    {
        float4 xw = *(const float4*)(g_XW + (size_t)cb * NG + m0 + 4 * cu);
        float i = sigf(xw.y), gg = tanhf(xw.z), o = sigf(xw.w);
        cc = i * gg;
        float h = o * tanhf(cc);
        out[(size_t)cb * HH + j0 + cu] = h;
        bf16 hh = __float2bfloat16(h);
        g_h2[0][cb * KK2 + j0 + cu]        = hh;
        g_h2[0][cb * KK2 + 1024 + j0 + cu] = __float2bfloat16(h - __bfloat162float(hh));
    }
    grid_barrier(0);

    const uint32_t d0 = sb + R_DOF;
    const uint32_t dk = d0 + (uint32_t)kg * R_DSZ;
    const uint32_t abase = sb + (uint32_t)((16 * mg + lrow) * R_PW) * 2;
    const int kk0 = kg * 4;
    for (int t = 1; t < TT; ++t) {
        const int rpar = (t - 1) & 1;
        const int wpar = t & 1;
        float acc[2][4] = {{0.f, 0.f, 0.f, 0.f}, {0.f, 0.f, 0.f, 0.f}};
        recur_issueB(sb, tid, 0, rpar);
        // prefetch this step's xw off the post-GEMM critical path
        float4 xw = *(const float4*)(g_XW + (size_t)t * BG + (size_t)cb * NG + m0 + 4 * cu);
        for (int ck = 0; ck < 8; ++ck) {
            if (ck < 7) { recur_issueB(sb, tid, ck + 1, rpar); CP_WAIT1(); }
            else CP_WAIT0();
            __syncthreads();
            uint32_t bb = sb + R_WB + (uint32_t)(ck & 1) * R_TB
                        + (uint32_t)((16 * ngp + lrow) * R_P) * 2;
            const int kc = ck * 128;
#pragma unroll
            for (int kk = 0; kk < 4; ++kk) {
                uint32_t aoff = abase + (uint32_t)(kc + (kk0 + kk) * 16 + lko) * 2;
                uint32_t boff = bb + (uint32_t)((kk0 + kk) * 16 + lko) * 2;
                uint32_t ah[4], al[4], bh[4], bl[4];
                ldm4(ah, aoff);
                ldm4(al, aoff + 1024 * 2);
                ldm4(bh, boff);
                ldm4(bl, boff + R_SPL);
                mma16816(acc[0], ah[0], ah[1], ah[2], ah[3], bh[0], bh[2]);
                mma16816(acc[1], ah[0], ah[1], ah[2], ah[3], bh[1], bh[3]);
                mma16816(acc[0], al[0], al[1], al[2], al[3], bh[0], bh[2]);
                mma16816(acc[1], al[0], al[1], al[2], al[3], bh[1], bh[3]);
                mma16816(acc[0], ah[0], ah[1], ah[2], ah[3], bl[0], bl[2]);
                mma16816(acc[1], ah[0], ah[1], ah[2], ah[3], bl[1], bl[3]);
            }
            __syncthreads();
        }
        // ---- stage D partial into this kg's smem buffer ----
#pragma unroll
        for (int s = 0; s < 2; ++s) {
            int r = 16 * mg + g;
            int nb = 16 * ngp + 8 * s + 2 * c4;
            sts_f32(dk + (uint32_t)(r * 65 + nb) * 4,           acc[s][0]);
            sts_f32(dk + (uint32_t)(r * 65 + nb + 1) * 4,       acc[s][1]);
            sts_f32(dk + (uint32_t)((r + 8) * 65 + nb) * 4,     acc[s][2]);
            sts_f32(dk + (uint32_t)((r + 8) * 65 + nb + 1) * 4, acc[s][3]);
        }
        __syncthreads();
        // ---- cell update: 1 cell per thread, sum the two k-split partials ----
        {
            float hf  = lds_f32(d0 + (uint32_t)((4 * cu + 0) * 65 + cb) * 4)
                      + lds_f32(d0 + R_DSZ + (uint32_t)((4 * cu + 0) * 65 + cb) * 4);
            float hi_ = lds_f32(d0 + (uint32_t)((4 * cu + 1) * 65 + cb) * 4)
                      + lds_f32(d0 + R_DSZ + (uint32_t)((4 * cu + 1) * 65 + cb) * 4);
            float hg  = lds_f32(d0 + (uint32_t)((4 * cu + 2) * 65 + cb) * 4)
                      + lds_f32(d0 + R_DSZ + (uint32_t)((4 * cu + 2) * 65 + cb) * 4);
            float ho  = lds_f32(d0 + (uint32_t)((4 * cu + 3) * 65 + cb) * 4)
                      + lds_f32(d0 + R_DSZ + (uint32_t)((4 * cu + 3) * 65 + cb) * 4);
            float f  = sigf(xw.x + hf);
            float i  = sigf(xw.y + hi_);
            float gg = tanhf(xw.z + hg);
            float o  = sigf(xw.w + ho);
            cc = f * cc + i * gg;
            float h = o * tanhf(cc);
            out[(size_t)t * BH + (size_t)cb * HH + j0 + cu] = h;
            bf16 hh = __float2bfloat16(h);
            g_h2[wpar][cb * KK2 + j0 + cu]        = hh;
            g_h2[wpar][cb * KK2 + 1024 + j0 + cu] = __float2bfloat16(h - __bfloat162float(hh));
            if (t == TT - 1) {
                out[(size_t)TT * BH + (size_t)cb * HH + j0 + cu] = h;          // hx
                out[(size_t)TT * BH + BH + (size_t)cb * HH + j0 + cu] = cc;    // cx
            }
        }
        if (t < TT - 1) grid_barrier(t);
    }
}

// ---------------- launch ----------------
extern "C" void kernel_launch(void* const* d_in, const int* in_sizes, int n_in,
                              void* d_out, int out_size) {
    const float* inputs = (const float*)d_in[0];
    const float* Wf = (const float*)d_in[1];
    const float* bf_ = (const float*)d_in[2];
    const float* Wi = (const float*)d_in[3];
    const float* bi_ = (const float*)d_in[4];
    const float* Wg = (const float*)d_in[5];
    const float* bg_ = (const float*)d_in[6];
    const float* Wo = (const float*)d_in[7];
    const float* bo_ = (const float*)d_in[8];
    float* out = (float*)d_out;
    (void)in_sizes; (void)n_in; (void)out_size;

    cudaFuncSetAttribute(xproj_kernel, cudaFuncAttributeMaxDynamicSharedMemorySize, X_SMEM);
    cudaFuncSetAttribute(recur_kernel, cudaFuncAttributeMaxDynamicSharedMemorySize, R_SMEM);

    // 1) repack (K-MAJOR convention — correct bias) + zero barriers
    repack_kernel<<<(KK * NG) / 256, 256>>>(Wf, Wi, Wg, Wo, bf_, bi_, bg_, bo_);

    // 2) split inputs into [hi|lo]
    convx_kernel<<<(TT * BB * KK) / 256, 256>>>(inputs);

    // 3) x-projections: ldmatrix fragment gathers
    xproj_kernel<<<dim3(32, 256), 256, X_SMEM>>>();

    // 4) persistent recurrence: 512 threads, 2-way k-split, xw prefetch
    recur_kernel<<<128, 512, R_SMEM>>>(out);
}